// round 9
// baseline (speedup 1.0000x reference)
#include <cuda_runtime.h>
#include <cuda_bf16.h>
#include <cstdint>

// Problem constants
#define NE 8
#define ND 1024
#define NF 4096
#define NT 8192
#define NC 2048
#define NM (NE * NC)   // 16384 rows through the expert FFN

// ---------------- scratch (device globals; no runtime allocation) ----------
__device__ float g_scoresT[NE * NT];              // gates^T  [E, T]
__device__ int   g_idx[NM];                       // selected token ids [E*C]
__device__ float g_vals[NM];                      // routing probs of selected
__device__ __nv_bfloat16 g_xh[(size_t)NT * ND];   // x split hi
__device__ __nv_bfloat16 g_xl[(size_t)NT * ND];   // x split lo
__device__ __nv_bfloat16 g_w1h[(size_t)NE * ND * NF];
__device__ __nv_bfloat16 g_w1l[(size_t)NE * ND * NF];
__device__ __nv_bfloat16 g_w2h[(size_t)NE * NF * ND];
__device__ __nv_bfloat16 g_w2l[(size_t)NE * NF * ND];
__device__ __nv_bfloat16 g_hh[(size_t)NM * NF];   // gelu output split hi
__device__ __nv_bfloat16 g_hl[(size_t)NM * NF];   // gelu output split lo

// ---------------- init output ------------------------------------------------
__global__ void init_out_kernel(float* out, size_t n_main, size_t total) {
    size_t i = (size_t)blockIdx.x * blockDim.x + threadIdx.x;
    size_t stride = (size_t)gridDim.x * blockDim.x;
    for (; i < total; i += stride) {
        if (i < n_main)       out[i] = 0.0f;
        else if (i == n_main) out[i] = 2.0f;   // aux_loss = E*(C/T)*1 = 2 analytically
        else                  out[i] = 0.0f;
    }
}

// ------------- fp32 -> (hi, lo) bf16 split, 16 floats/thread, MLP=4 ---------
__global__ void split_kernel(const float4* __restrict__ in,
                             uint4* __restrict__ hi,
                             uint4* __restrict__ lo, size_t n16) {
    size_t i = (size_t)blockIdx.x * blockDim.x + threadIdx.x;
    if (i >= n16) return;
    float4 a0 = in[4 * i];
    float4 a1 = in[4 * i + 1];
    float4 a2 = in[4 * i + 2];
    float4 a3 = in[4 * i + 3];
    float v[16] = {a0.x, a0.y, a0.z, a0.w, a1.x, a1.y, a1.z, a1.w,
                   a2.x, a2.y, a2.z, a2.w, a3.x, a3.y, a3.z, a3.w};
    __nv_bfloat162 h[8], l[8];
#pragma unroll
    for (int j = 0; j < 8; j++) {
        float v0 = v[2 * j], v1 = v[2 * j + 1];
        h[j] = __floats2bfloat162_rn(v0, v1);
        l[j] = __floats2bfloat162_rn(v0 - __bfloat162float(h[j].x),
                                     v1 - __bfloat162float(h[j].y));
    }
    hi[2 * i]     = *(const uint4*)&h[0];
    hi[2 * i + 1] = *(const uint4*)&h[4];
    lo[2 * i]     = *(const uint4*)&l[0];
    lo[2 * i + 1] = *(const uint4*)&l[4];
}

// ---------------- router: gates = softmax(x @ Wg), stored transposed --------
__global__ void router_kernel(const float* __restrict__ x,
                              const float* __restrict__ Wg) {
    int warp = (blockIdx.x * blockDim.x + threadIdx.x) >> 5;
    int lane = threadIdx.x & 31;
    if (warp >= NT) return;
    const float* xr = x + (size_t)warp * ND;
    float acc[NE];
#pragma unroll
    for (int e = 0; e < NE; e++) acc[e] = 0.0f;
    for (int d = lane; d < ND; d += 32) {
        float xv = xr[d];
        const float4 w0 = *(const float4*)(Wg + d * NE);
        const float4 w1 = *(const float4*)(Wg + d * NE + 4);
        acc[0] += xv * w0.x; acc[1] += xv * w0.y;
        acc[2] += xv * w0.z; acc[3] += xv * w0.w;
        acc[4] += xv * w1.x; acc[5] += xv * w1.y;
        acc[6] += xv * w1.z; acc[7] += xv * w1.w;
    }
#pragma unroll
    for (int off = 16; off > 0; off >>= 1) {
#pragma unroll
        for (int e = 0; e < NE; e++)
            acc[e] += __shfl_down_sync(0xffffffffu, acc[e], off);
    }
    if (lane == 0) {
        float m = acc[0];
#pragma unroll
        for (int e = 1; e < NE; e++) m = fmaxf(m, acc[e]);
        float s = 0.0f;
#pragma unroll
        for (int e = 0; e < NE; e++) { acc[e] = expf(acc[e] - m); s += acc[e]; }
        float inv = 1.0f / s;
#pragma unroll
        for (int e = 0; e < NE; e++) g_scoresT[e * NT + warp] = acc[e] * inv;
    }
}

// ---------------- exact top-C per expert via 4-pass radix select ------------
__global__ void topk_kernel() {
    int e = blockIdx.x;
    int tid = threadIdx.x;
    const float* s = g_scoresT + e * NT;

    __shared__ unsigned hist[256];
    __shared__ unsigned sh_prefix;
    __shared__ int sh_rem;

    unsigned prefix = 0;
    int remaining = NC;

    for (int shift = 24; shift >= 0; shift -= 8) {
        if (tid < 256) hist[tid] = 0;
        __syncthreads();
        unsigned mask = (shift == 24) ? 0u : (0xFFFFFFFFu << (shift + 8));
        for (int t = tid; t < NT; t += blockDim.x) {
            unsigned k = __float_as_uint(s[t]);
            if ((k & mask) == prefix) atomicAdd(&hist[(k >> shift) & 0xFFu], 1u);
        }
        __syncthreads();
        if (tid == 0) {
            int rem = remaining;
            int b = 0;
            for (int d = 255; d >= 0; d--) {
                int h = (int)hist[d];
                if (h >= rem) { b = d; break; }
                rem -= h;
            }
            sh_prefix = prefix | ((unsigned)b << shift);
            sh_rem = rem;
        }
        __syncthreads();
        prefix = sh_prefix;
        remaining = sh_rem;
        __syncthreads();
    }

    __shared__ int cnt_gt, cnt_eq;
    if (tid == 0) { cnt_gt = 0; cnt_eq = 0; }
    __syncthreads();
    int base = NC - remaining;
    for (int t = tid; t < NT; t += blockDim.x) {
        unsigned k = __float_as_uint(s[t]);
        if (k > prefix) {
            int p = atomicAdd(&cnt_gt, 1);
            g_idx[e * NC + p]  = t;
            g_vals[e * NC + p] = s[t];
        } else if (k == prefix) {
            int p = atomicAdd(&cnt_eq, 1);
            if (p < remaining) {
                g_idx[e * NC + base + p]  = t;
                g_vals[e * NC + base + p] = s[t];
            }
        }
    }
}

// ---------------- gelu (tanh approx via fast exp; matches jax to ~1e-6) -----
__device__ __forceinline__ float gelu_f(float v) {
    float u = 0.7978845608028654f * (v + 0.044715f * v * v * v);
    float t = 1.0f - 2.0f / (__expf(2.0f * u) + 1.0f);
    return 0.5f * v * (1.0f + t);
}

// ============================ 3xBF16 mma.sync GEMM ============================
// CTA tile 128(M) x 256(N) x 32(K). 512 threads, 16 warps 2(m) x 8(n),
// warp tile 64x32. hi*hi + lo*hi + hi*lo on m16n8k16.bf16, all f32 accum.
// 4-stage cp.async pipeline (prefetch distance 3, wait_group 2), ONE
// __syncthreads per chunk (top barrier alone guards stage reuse).

static constexpr int A_STRIDE = 40;                 // bf16 units (80 B)
static constexpr int A_PLANE  = 128 * A_STRIDE;     // 5120
static constexpr int A_STAGE  = 2 * A_PLANE;        // hi + lo = 10240
static constexpr int B_BASE   = 4 * A_STAGE;        // 40960
static constexpr int B_STRIDE = 264;                // bf16 units (528 B)
static constexpr int B_PLANE  = 32 * B_STRIDE;      // 8448
static constexpr int B_STAGE  = 2 * B_PLANE;        // 16896
static constexpr int SMEM_BF16 = B_BASE + 4 * B_STAGE;       // 108544
static constexpr int GEMM_SMEM_BYTES = SMEM_BF16 * 2;        // 217088

__device__ __forceinline__ uint32_t smem_u32(const void* p) {
    uint32_t a;
    asm("{ .reg .u64 t; cvta.to.shared.u64 t, %1; cvt.u32.u64 %0, t; }"
        : "=r"(a) : "l"(p));
    return a;
}

__device__ __forceinline__ void cp16(uint32_t dst, const void* src) {
    asm volatile("cp.async.cg.shared.global [%0], [%1], 16;"
                 :: "r"(dst), "l"(src) : "memory");
}
#define CP_COMMIT() asm volatile("cp.async.commit_group;" ::: "memory")
#define CP_WAIT2()  asm volatile("cp.async.wait_group 2;" ::: "memory")

__device__ __forceinline__ void ldsm4(uint32_t* r, uint32_t addr) {
    asm volatile("ldmatrix.sync.aligned.m8n8.x4.shared.b16 {%0,%1,%2,%3}, [%4];"
                 : "=r"(r[0]), "=r"(r[1]), "=r"(r[2]), "=r"(r[3]) : "r"(addr));
}
__device__ __forceinline__ void ldsm4t(uint32_t* r, uint32_t addr) {
    asm volatile("ldmatrix.sync.aligned.m8n8.x4.trans.shared.b16 {%0,%1,%2,%3}, [%4];"
                 : "=r"(r[0]), "=r"(r[1]), "=r"(r[2]), "=r"(r[3]) : "r"(addr));
}

__device__ __forceinline__ void mma_bf16(float* d, const uint32_t* a,
                                         const uint32_t* b) {
    asm volatile(
        "mma.sync.aligned.m16n8k16.row.col.f32.bf16.bf16.f32 "
        "{%0,%1,%2,%3}, {%4,%5,%6,%7}, {%8,%9}, {%0,%1,%2,%3};"
        : "+f"(d[0]), "+f"(d[1]), "+f"(d[2]), "+f"(d[3])
        : "r"(a[0]), "r"(a[1]), "r"(a[2]), "r"(a[3]), "r"(b[0]), "r"(b[1]));
}

__device__ __forceinline__ void red_v2(float* ptr, float v0, float v1) {
    asm volatile("red.global.add.v2.f32 [%0], {%1, %2};"
                 :: "l"(ptr), "f"(v0), "f"(v1) : "memory");
}

// NCH chunks of K=32 per CTA per K-slice. GATHER: A rows via g_idx (lda=ND).
// GELU_EPI: write split-bf16 gelu(acc+bias); else scatter-add into fp32 outa.
// blockIdx.z = K-slice; slice 0 adds bias. Ktot = full K (B expert stride).
template<int NCH, bool GATHER, bool GELU_EPI>
__global__ __launch_bounds__(512) void gemm_tc_kernel(
    const __nv_bfloat16* __restrict__ Ah,
    const __nv_bfloat16* __restrict__ Al,
    const __nv_bfloat16* __restrict__ Bh,
    const __nv_bfloat16* __restrict__ Bl,
    const float* __restrict__ bias,
    float* __restrict__ outa,
    __nv_bfloat16* __restrict__ outbh,
    __nv_bfloat16* __restrict__ outbl,
    int Nld, int lda, int Ktot) {
    extern __shared__ __align__(16) __nv_bfloat16 sm[];
    __shared__ int   tok_s[128];
    __shared__ float val_s[128];

    const int tid = threadIdx.x;
    const int warp = tid >> 5;
    const int lane = tid & 31;
    const int wm = warp >> 3;          // 0..1  (64-row slab)
    const int wn = warp & 7;           // 0..7  (32-col slab)
    const int r = lane >> 2;           // 0..7 (accumulator row)
    const int c = lane & 3;            // 0..3 (accumulator col pair)
    const int quad = lane >> 3;        // 0..3 (ldmatrix matrix id)
    const int r8 = lane & 7;           // row within 8x8 matrix

    const int n0 = blockIdx.x * 256;
    const int m0 = blockIdx.y * 128;
    const int e = m0 >> 11;            // m0 / NC
    const int kbase = blockIdx.z * NCH * 32;
    const bool bias_en = (blockIdx.z == 0);

    if (tid < 128) {
        tok_s[tid] = g_idx[m0 + tid];
        val_s[tid] = g_vals[m0 + tid];
    }
    __syncthreads();

    const uint32_t sbase = smem_u32(sm);

    // ---- precomputed load pointers (advance one K-chunk per load_stage) ----
    const __nv_bfloat16* asrc[2];
    uint32_t adst0[2];
    const __nv_bfloat16* bsrc[4];
    uint32_t bdst0[4];
    {
        const __nv_bfloat16* aps[2] = {Ah, Al};
        const size_t bexp = (size_t)e * Ktot * Nld + n0;
        const __nv_bfloat16* bps[2] = {Bh + bexp, Bl + bexp};
        const int arow = tid >> 2;
        const int aseg = (tid & 3) * 8;
#pragma unroll
        for (int p = 0; p < 2; p++) {
            asrc[p] = GATHER
                ? (aps[p] + (size_t)tok_s[arow] * lda + kbase + aseg)
                : (aps[p] + (size_t)(m0 + arow) * lda + kbase + aseg);
            adst0[p] = sbase + (uint32_t)(p * A_PLANE + arow * A_STRIDE + aseg) * 2;
#pragma unroll
            for (int i = 0; i < 2; i++) {
                int lin = tid + 512 * i;
                int row = lin >> 5;
                int seg = (lin & 31) * 8;
                int j = p * 2 + i;
                bsrc[j] = bps[p] + (size_t)(kbase + row) * Nld + seg;
                bdst0[j] = sbase + (uint32_t)(B_BASE + p * B_PLANE +
                                              row * B_STRIDE + seg) * 2;
            }
        }
    }

    auto load_stage = [&](int s) {
        const uint32_t ao = (uint32_t)s * (A_STAGE * 2);
        const uint32_t bo = (uint32_t)s * (B_STAGE * 2);
#pragma unroll
        for (int j = 0; j < 2; j++) {
            cp16(adst0[j] + ao, asrc[j]);
            asrc[j] += 32;
        }
#pragma unroll
        for (int j = 0; j < 4; j++) {
            cp16(bdst0[j] + bo, bsrc[j]);
            bsrc[j] += (size_t)32 * Nld;
        }
    };

    float acc[4][4][4];                // [mt][nt][frag]
#pragma unroll
    for (int mt = 0; mt < 4; mt++)
#pragma unroll
        for (int nt = 0; nt < 4; nt++)
#pragma unroll
            for (int i = 0; i < 4; i++) acc[mt][nt][i] = 0.0f;

    // prologue: fill stages 0, 1, 2 (prefetch distance 3)
    load_stage(0);
    CP_COMMIT();
    load_stage(1);
    CP_COMMIT();
    load_stage(2);
    CP_COMMIT();

#pragma unroll 1
    for (int ch = 0; ch < NCH; ch++) {
        const int s = ch & 3;
        CP_WAIT2();
        __syncthreads();               // single barrier: also guards stage reuse
        if (ch + 3 < NCH) load_stage((ch + 3) & 3);
        CP_COMMIT();   // unconditional: keeps wait_group bookkeeping exact

        const uint32_t sa = sbase + (uint32_t)s * (A_STAGE * 2);
        const uint32_t sb = sbase + (uint32_t)(B_BASE * 2 + s * (B_STAGE * 2));
#pragma unroll
        for (int ks = 0; ks < 2; ks++) {
            // ---- A fragments: hi/lo x 4 m-tiles via ldmatrix.x4 ----
            uint32_t ah[4][4], al[4][4];
            {
                const int m_local = wm * 64 + (quad & 1) * 8 + r8;
                const int k_off = ks * 16 + (quad >> 1) * 8;
                const uint32_t abase = sa +
                    (uint32_t)(m_local * A_STRIDE + k_off) * 2;
#pragma unroll
                for (int mt = 0; mt < 4; mt++) {
                    ldsm4(ah[mt], abase + (uint32_t)(mt * 16 * A_STRIDE) * 2);
                    ldsm4(al[mt], abase + (uint32_t)(A_PLANE + mt * 16 * A_STRIDE) * 2);
                }
            }
            // ---- B fragments per 16-col group, then MMAs ----
            {
                const int k_row = ks * 16 + (quad & 1) * 8 + r8;
                const int n_col = wn * 32 + (quad >> 1) * 8;
                const uint32_t bbase = sb +
                    (uint32_t)(k_row * B_STRIDE + n_col) * 2;
#pragma unroll
                for (int nt2 = 0; nt2 < 2; nt2++) {
                    uint32_t bh[4], bl[4];
                    ldsm4t(bh, bbase + (uint32_t)(nt2 * 16) * 2);
                    ldsm4t(bl, bbase + (uint32_t)(B_PLANE + nt2 * 16) * 2);
                    const int nt = nt2 * 2;
#pragma unroll
                    for (int mt = 0; mt < 4; mt++) {
                        mma_bf16(acc[mt][nt],     ah[mt], bh);        // hi*hi
                        mma_bf16(acc[mt][nt],     al[mt], bh);        // lo*hi
                        mma_bf16(acc[mt][nt],     ah[mt], bl);        // hi*lo
                        mma_bf16(acc[mt][nt + 1], ah[mt], bh + 2);
                        mma_bf16(acc[mt][nt + 1], al[mt], bh + 2);
                        mma_bf16(acc[mt][nt + 1], ah[mt], bl + 2);
                    }
                }
            }
        }
    }

    // ---------------- epilogue -----------------------------------------------
#pragma unroll
    for (int mt = 0; mt < 4; mt++) {
        const int lm0 = wm * 64 + mt * 16 + r;       // local row of acc[0],acc[1]
        const int lm1 = lm0 + 8;                     // local row of acc[2],acc[3]
#pragma unroll
        for (int nt = 0; nt < 4; nt++) {
            const int bcol = n0 + wn * 32 + nt * 8 + c * 2;
            const float bb0 = bias_en ? bias[e * Nld + bcol] : 0.0f;
            const float bb1 = bias_en ? bias[e * Nld + bcol + 1] : 0.0f;
            if (GELU_EPI) {
                float v00 = gelu_f(acc[mt][nt][0] + bb0);
                float v01 = gelu_f(acc[mt][nt][1] + bb1);
                float v10 = gelu_f(acc[mt][nt][2] + bb0);
                float v11 = gelu_f(acc[mt][nt][3] + bb1);
                __nv_bfloat162 h0, h1, l0, l1;
                h0.x = __float2bfloat16_rn(v00);
                h0.y = __float2bfloat16_rn(v01);
                h1.x = __float2bfloat16_rn(v10);
                h1.y = __float2bfloat16_rn(v11);
                l0.x = __float2bfloat16_rn(v00 - __bfloat162float(h0.x));
                l0.y = __float2bfloat16_rn(v01 - __bfloat162float(h0.y));
                l1.x = __float2bfloat16_rn(v10 - __bfloat162float(h1.x));
                l1.y = __float2bfloat16_rn(v11 - __bfloat162float(h1.y));
                *(__nv_bfloat162*)(outbh + (size_t)(m0 + lm0) * Nld + bcol) = h0;
                *(__nv_bfloat162*)(outbh + (size_t)(m0 + lm1) * Nld + bcol) = h1;
                *(__nv_bfloat162*)(outbl + (size_t)(m0 + lm0) * Nld + bcol) = l0;
                *(__nv_bfloat162*)(outbl + (size_t)(m0 + lm1) * Nld + bcol) = l1;
            } else {
                const float w0 = val_s[lm0];
                const float w1 = val_s[lm1];
                float* p0 = outa + (size_t)tok_s[lm0] * ND + bcol;
                float* p1 = outa + (size_t)tok_s[lm1] * ND + bcol;
                red_v2(p0, (acc[mt][nt][0] + bb0) * w0, (acc[mt][nt][1] + bb1) * w0);
                red_v2(p1, (acc[mt][nt][2] + bb0) * w1, (acc[mt][nt][3] + bb1) * w1);
            }
        }
    }
}

// ============================ host launch =====================================
extern "C" void kernel_launch(void* const* d_in, const int* in_sizes, int n_in,
                              void* d_out, int out_size) {
    const float* x  = (const float*)d_in[0];   // [T, D]
    const float* Wg = (const float*)d_in[1];   // [D, E]
    const float* W1 = (const float*)d_in[2];   // [E, D, F]
    const float* b1 = (const float*)d_in[3];   // [E, F]
    const float* W2 = (const float*)d_in[4];   // [E, F, D]
    const float* b2 = (const float*)d_in[5];   // [E, D]
    float* out = (float*)d_out;

    void *p_xh, *p_xl, *p_w1h, *p_w1l, *p_w2h, *p_w2l, *p_hh, *p_hl;
    cudaGetSymbolAddress(&p_xh, g_xh);
    cudaGetSymbolAddress(&p_xl, g_xl);
    cudaGetSymbolAddress(&p_w1h, g_w1h);
    cudaGetSymbolAddress(&p_w1l, g_w1l);
    cudaGetSymbolAddress(&p_w2h, g_w2h);
    cudaGetSymbolAddress(&p_w2l, g_w2l);
    cudaGetSymbolAddress(&p_hh, g_hh);
    cudaGetSymbolAddress(&p_hl, g_hl);

    cudaFuncSetAttribute((const void*)gemm_tc_kernel<32, true, true>,
                         cudaFuncAttributeMaxDynamicSharedMemorySize,
                         GEMM_SMEM_BYTES);
    cudaFuncSetAttribute((const void*)gemm_tc_kernel<64, false, false>,
                         cudaFuncAttributeMaxDynamicSharedMemorySize,
                         GEMM_SMEM_BYTES);

    size_t n_main = (size_t)NT * ND;
    init_out_kernel<<<512, 256>>>(out, n_main, (size_t)out_size);
    router_kernel<<<NT / 32, 1024>>>(x, Wg);
    topk_kernel<<<NE, 1024>>>();

    // Pre-split operands into bf16 hi/lo planes, 16 floats/thread.
    split_kernel<<<(NT * ND / 16 + 255) / 256, 256>>>(
        (const float4*)x, (uint4*)p_xh, (uint4*)p_xl, (size_t)NT * ND / 16);
    split_kernel<<<((size_t)NE * ND * NF / 16 + 255) / 256, 256>>>(
        (const float4*)W1, (uint4*)p_w1h, (uint4*)p_w1l,
        (size_t)NE * ND * NF / 16);
    split_kernel<<<((size_t)NE * NF * ND / 16 + 255) / 256, 256>>>(
        (const float4*)W2, (uint4*)p_w2h, (uint4*)p_w2l,
        (size_t)NE * NF * ND / 16);

    // GEMM1: h = gelu(x[idx] @ W1[e] + b1[e])   M=16384, N=4096, K=1024
    gemm_tc_kernel<32, true, true>
        <<<dim3(NF / 256, NM / 128, 1), 512, GEMM_SMEM_BYTES>>>(
            (const __nv_bfloat16*)p_xh, (const __nv_bfloat16*)p_xl,
            (const __nv_bfloat16*)p_w1h, (const __nv_bfloat16*)p_w1l,
            b1, nullptr,
            (__nv_bfloat16*)p_hh, (__nv_bfloat16*)p_hl, NF, ND, ND);

    // GEMM2: out[tok] += val*(h @ W2[e] + b2[e])  M=16384, N=1024, K=4096
    // split-K = 2 (epilogue is scatter-add, so K-slices both reduce in)
    gemm_tc_kernel<64, false, false>
        <<<dim3(ND / 256, NM / 128, 2), 512, GEMM_SMEM_BYTES>>>(
            (const __nv_bfloat16*)p_hh, (const __nv_bfloat16*)p_hl,
            (const __nv_bfloat16*)p_w2h, (const __nv_bfloat16*)p_w2l,
            b2, out, nullptr, nullptr, ND, NF, NF);
}

// round 12
// speedup vs baseline: 1.0847x; 1.0847x over previous
#include <cuda_runtime.h>
#include <cuda_bf16.h>
#include <cstdint>

// Problem constants
#define NE 8
#define ND 1024
#define NF 4096
#define NT 8192
#define NC 2048
#define NM (NE * NC)   // 16384 rows through the expert FFN

// ---------------- scratch (device globals; no runtime allocation) ----------
__device__ float g_scoresT[NE * NT];              // gates^T  [E, T]
__device__ int   g_idx[NM];                       // selected token ids [E*C]
__device__ float g_vals[NM];                      // routing probs of selected
__device__ __nv_bfloat16 g_xh[(size_t)NT * ND];   // x split hi
__device__ __nv_bfloat16 g_xl[(size_t)NT * ND];   // x split lo
__device__ __nv_bfloat16 g_w1h[(size_t)NE * ND * NF];
__device__ __nv_bfloat16 g_w1l[(size_t)NE * ND * NF];
__device__ __nv_bfloat16 g_w2h[(size_t)NE * NF * ND];
__device__ __nv_bfloat16 g_w2l[(size_t)NE * NF * ND];
__device__ __nv_bfloat16 g_hh[(size_t)NM * NF];   // gelu output split hi
__device__ __nv_bfloat16 g_hl[(size_t)NM * NF];   // gelu output split lo

// ---------------- init output ------------------------------------------------
__global__ void init_out_kernel(float* out, size_t n_main, size_t total) {
    size_t i = (size_t)blockIdx.x * blockDim.x + threadIdx.x;
    size_t stride = (size_t)gridDim.x * blockDim.x;
    for (; i < total; i += stride) {
        if (i < n_main)       out[i] = 0.0f;
        else if (i == n_main) out[i] = 2.0f;   // aux_loss = E*(C/T)*1 = 2 analytically
        else                  out[i] = 0.0f;
    }
}

// ---------------- fp32 -> (hi, lo) bf16 split, 8 floats/thread --------------
__global__ void split_kernel(const float4* __restrict__ in,
                             uint4* __restrict__ hi,
                             uint4* __restrict__ lo, size_t n8) {
    size_t i = (size_t)blockIdx.x * blockDim.x + threadIdx.x;
    if (i >= n8) return;
    float4 a = in[2 * i];
    float4 b = in[2 * i + 1];
    __nv_bfloat162 h[4], l[4];
    h[0] = __floats2bfloat162_rn(a.x, a.y);
    h[1] = __floats2bfloat162_rn(a.z, a.w);
    h[2] = __floats2bfloat162_rn(b.x, b.y);
    h[3] = __floats2bfloat162_rn(b.z, b.w);
    l[0] = __floats2bfloat162_rn(a.x - __bfloat162float(h[0].x),
                                 a.y - __bfloat162float(h[0].y));
    l[1] = __floats2bfloat162_rn(a.z - __bfloat162float(h[1].x),
                                 a.w - __bfloat162float(h[1].y));
    l[2] = __floats2bfloat162_rn(b.x - __bfloat162float(h[2].x),
                                 b.y - __bfloat162float(h[2].y));
    l[3] = __floats2bfloat162_rn(b.z - __bfloat162float(h[3].x),
                                 b.w - __bfloat162float(h[3].y));
    hi[i] = *(const uint4*)h;
    lo[i] = *(const uint4*)l;
}

// ---------------- router: gates = softmax(x @ Wg), stored transposed --------
__global__ void router_kernel(const float* __restrict__ x,
                              const float* __restrict__ Wg) {
    int warp = (blockIdx.x * blockDim.x + threadIdx.x) >> 5;
    int lane = threadIdx.x & 31;
    if (warp >= NT) return;
    const float* xr = x + (size_t)warp * ND;
    float acc[NE];
#pragma unroll
    for (int e = 0; e < NE; e++) acc[e] = 0.0f;
    for (int d = lane; d < ND; d += 32) {
        float xv = xr[d];
        const float4 w0 = *(const float4*)(Wg + d * NE);
        const float4 w1 = *(const float4*)(Wg + d * NE + 4);
        acc[0] += xv * w0.x; acc[1] += xv * w0.y;
        acc[2] += xv * w0.z; acc[3] += xv * w0.w;
        acc[4] += xv * w1.x; acc[5] += xv * w1.y;
        acc[6] += xv * w1.z; acc[7] += xv * w1.w;
    }
#pragma unroll
    for (int off = 16; off > 0; off >>= 1) {
#pragma unroll
        for (int e = 0; e < NE; e++)
            acc[e] += __shfl_down_sync(0xffffffffu, acc[e], off);
    }
    if (lane == 0) {
        float m = acc[0];
#pragma unroll
        for (int e = 1; e < NE; e++) m = fmaxf(m, acc[e]);
        float s = 0.0f;
#pragma unroll
        for (int e = 0; e < NE; e++) { acc[e] = expf(acc[e] - m); s += acc[e]; }
        float inv = 1.0f / s;
#pragma unroll
        for (int e = 0; e < NE; e++) g_scoresT[e * NT + warp] = acc[e] * inv;
    }
}

// ---------------- exact top-C per expert via 4-pass radix select ------------
__global__ void topk_kernel() {
    int e = blockIdx.x;
    int tid = threadIdx.x;
    const float* s = g_scoresT + e * NT;

    __shared__ unsigned hist[256];
    __shared__ unsigned sh_prefix;
    __shared__ int sh_rem;

    unsigned prefix = 0;
    int remaining = NC;

    for (int shift = 24; shift >= 0; shift -= 8) {
        if (tid < 256) hist[tid] = 0;
        __syncthreads();
        unsigned mask = (shift == 24) ? 0u : (0xFFFFFFFFu << (shift + 8));
        for (int t = tid; t < NT; t += blockDim.x) {
            unsigned k = __float_as_uint(s[t]);
            if ((k & mask) == prefix) atomicAdd(&hist[(k >> shift) & 0xFFu], 1u);
        }
        __syncthreads();
        if (tid == 0) {
            int rem = remaining;
            int b = 0;
            for (int d = 255; d >= 0; d--) {
                int h = (int)hist[d];
                if (h >= rem) { b = d; break; }
                rem -= h;
            }
            sh_prefix = prefix | ((unsigned)b << shift);
            sh_rem = rem;
        }
        __syncthreads();
        prefix = sh_prefix;
        remaining = sh_rem;
        __syncthreads();
    }

    __shared__ int cnt_gt, cnt_eq;
    if (tid == 0) { cnt_gt = 0; cnt_eq = 0; }
    __syncthreads();
    int base = NC - remaining;
    for (int t = tid; t < NT; t += blockDim.x) {
        unsigned k = __float_as_uint(s[t]);
        if (k > prefix) {
            int p = atomicAdd(&cnt_gt, 1);
            g_idx[e * NC + p]  = t;
            g_vals[e * NC + p] = s[t];
        } else if (k == prefix) {
            int p = atomicAdd(&cnt_eq, 1);
            if (p < remaining) {
                g_idx[e * NC + base + p]  = t;
                g_vals[e * NC + base + p] = s[t];
            }
        }
    }
}

// ---------------- gelu (tanh approx via fast exp; matches jax to ~1e-6) -----
__device__ __forceinline__ float gelu_f(float v) {
    float u = 0.7978845608028654f * (v + 0.044715f * v * v * v);
    float t = 1.0f - 2.0f / (__expf(2.0f * u) + 1.0f);
    return 0.5f * v * (1.0f + t);
}

// ============================ 3xBF16 mma.sync GEMM ============================
// CTA tile 128(M) x 128(N) x 32(K). 256 threads, 8 warps 2(m) x 4(n),
// warp tile 64x32. hi*hi + lo*hi + hi*lo on m16n8k16.bf16, all f32 accum.
// 3-stage cp.async pipeline, single top barrier, TWO CTAs PER SM so that
// barriers/epilogues of one CTA overlap the other CTA's MMA stream.
// B_STRIDE = 136 units = 272 B (16B-aligned; row bank offset 4 -> no conflicts).

static constexpr int A_STRIDE = 40;                 // bf16 units (80 B)
static constexpr int A_PLANE  = 128 * A_STRIDE;     // 5120
static constexpr int A_STAGE  = 2 * A_PLANE;        // hi + lo = 10240
static constexpr int B_BASE   = 3 * A_STAGE;        // 30720
static constexpr int B_STRIDE = 136;                // bf16 units (272 B, 17*16)
static constexpr int B_PLANE  = 32 * B_STRIDE;      // 4352
static constexpr int B_STAGE  = 2 * B_PLANE;        // 8704
static constexpr int SMEM_BF16 = B_BASE + 3 * B_STAGE;       // 56832
static constexpr int GEMM_SMEM_BYTES = SMEM_BF16 * 2;        // 113664

__device__ __forceinline__ uint32_t smem_u32(const void* p) {
    uint32_t a;
    asm("{ .reg .u64 t; cvta.to.shared.u64 t, %1; cvt.u32.u64 %0, t; }"
        : "=r"(a) : "l"(p));
    return a;
}

__device__ __forceinline__ void cp16(uint32_t dst, const void* src) {
    asm volatile("cp.async.cg.shared.global [%0], [%1], 16;"
                 :: "r"(dst), "l"(src) : "memory");
}
#define CP_COMMIT() asm volatile("cp.async.commit_group;" ::: "memory")
#define CP_WAIT1()  asm volatile("cp.async.wait_group 1;" ::: "memory")

__device__ __forceinline__ void ldsm4(uint32_t* r, uint32_t addr) {
    asm volatile("ldmatrix.sync.aligned.m8n8.x4.shared.b16 {%0,%1,%2,%3}, [%4];"
                 : "=r"(r[0]), "=r"(r[1]), "=r"(r[2]), "=r"(r[3]) : "r"(addr));
}
__device__ __forceinline__ void ldsm4t(uint32_t* r, uint32_t addr) {
    asm volatile("ldmatrix.sync.aligned.m8n8.x4.trans.shared.b16 {%0,%1,%2,%3}, [%4];"
                 : "=r"(r[0]), "=r"(r[1]), "=r"(r[2]), "=r"(r[3]) : "r"(addr));
}

__device__ __forceinline__ void mma_bf16(float* d, const uint32_t* a,
                                         const uint32_t* b) {
    asm volatile(
        "mma.sync.aligned.m16n8k16.row.col.f32.bf16.bf16.f32 "
        "{%0,%1,%2,%3}, {%4,%5,%6,%7}, {%8,%9}, {%0,%1,%2,%3};"
        : "+f"(d[0]), "+f"(d[1]), "+f"(d[2]), "+f"(d[3])
        : "r"(a[0]), "r"(a[1]), "r"(a[2]), "r"(a[3]), "r"(b[0]), "r"(b[1]));
}

__device__ __forceinline__ void red_v2(float* ptr, float v0, float v1) {
    asm volatile("red.global.add.v2.f32 [%0], {%1, %2};"
                 :: "l"(ptr), "f"(v0), "f"(v1) : "memory");
}

// NCH chunks of K=32 per CTA per K-slice. GATHER: A rows via g_idx (lda=ND).
// GELU_EPI: write split-bf16 gelu(acc+bias); else scatter-add into fp32 outa.
// blockIdx.z = K-slice; slice 0 adds bias. Ktot = full K (B expert stride).
template<int NCH, bool GATHER, bool GELU_EPI>
__global__ __launch_bounds__(256, 2) void gemm_tc_kernel(
    const __nv_bfloat16* __restrict__ Ah,
    const __nv_bfloat16* __restrict__ Al,
    const __nv_bfloat16* __restrict__ Bh,
    const __nv_bfloat16* __restrict__ Bl,
    const float* __restrict__ bias,
    float* __restrict__ outa,
    __nv_bfloat16* __restrict__ outbh,
    __nv_bfloat16* __restrict__ outbl,
    int Nld, int lda, int Ktot) {
    extern __shared__ __align__(16) __nv_bfloat16 sm[];
    __shared__ int   tok_s[128];
    __shared__ float val_s[128];

    const int tid = threadIdx.x;
    const int warp = tid >> 5;
    const int lane = tid & 31;
    const int wm = warp >> 2;          // 0..1  (64-row slab)
    const int wn = warp & 3;           // 0..3  (32-col slab)
    const int r = lane >> 2;           // 0..7 (accumulator row)
    const int c = lane & 3;            // 0..3 (accumulator col pair)
    const int quad = lane >> 3;        // 0..3 (ldmatrix matrix id)
    const int r8 = lane & 7;           // row within 8x8 matrix

    const int n0 = blockIdx.x * 128;
    const int m0 = blockIdx.y * 128;
    const int e = m0 >> 11;            // m0 / NC
    const int kbase = blockIdx.z * NCH * 32;
    const bool bias_en = (blockIdx.z == 0);

    if (tid < 128) {
        tok_s[tid] = g_idx[m0 + tid];
        val_s[tid] = g_vals[m0 + tid];
    }
    __syncthreads();

    const uint32_t sbase = smem_u32(sm);

    // ---- precomputed load pointers (advance one K-chunk per load_stage) ----
    const __nv_bfloat16* asrc[4];      // 2 planes x 2 iterations (A: 512 cp16)
    uint32_t adst0[4];
    const __nv_bfloat16* bsrc[4];      // 2 planes x 2 iterations (B: 512 cp16)
    uint32_t bdst0[4];
    {
        const __nv_bfloat16* aps[2] = {Ah, Al};
        const size_t bexp = (size_t)e * Ktot * Nld + n0;
        const __nv_bfloat16* bps[2] = {Bh + bexp, Bl + bexp};
#pragma unroll
        for (int p = 0; p < 2; p++) {
#pragma unroll
            for (int i = 0; i < 2; i++) {          // A: 128 rows x 4 segs
                int lin = tid + 256 * i;
                int row = lin >> 2;
                int seg = (lin & 3) * 8;
                int j = p * 2 + i;
                asrc[j] = GATHER
                    ? (aps[p] + (size_t)tok_s[row] * lda + kbase + seg)
                    : (aps[p] + (size_t)(m0 + row) * lda + kbase + seg);
                adst0[j] = sbase + (uint32_t)(p * A_PLANE + row * A_STRIDE + seg) * 2;
            }
#pragma unroll
            for (int i = 0; i < 2; i++) {          // B: 32 rows x 16 segs
                int lin = tid + 256 * i;
                int row = lin >> 4;                // 0..31
                int seg = (lin & 15) * 8;
                int j = p * 2 + i;
                bsrc[j] = bps[p] + (size_t)(kbase + row) * Nld + seg;
                bdst0[j] = sbase + (uint32_t)(B_BASE + p * B_PLANE +
                                              row * B_STRIDE + seg) * 2;
            }
        }
    }

    auto load_stage = [&](int s) {
        const uint32_t ao = (uint32_t)s * (A_STAGE * 2);
        const uint32_t bo = (uint32_t)s * (B_STAGE * 2);
#pragma unroll
        for (int j = 0; j < 4; j++) {
            cp16(adst0[j] + ao, asrc[j]);
            asrc[j] += 32;
        }
#pragma unroll
        for (int j = 0; j < 4; j++) {
            cp16(bdst0[j] + bo, bsrc[j]);
            bsrc[j] += (size_t)32 * Nld;
        }
    };

    float acc[4][4][4];                // [mt][nt][frag]
#pragma unroll
    for (int mt = 0; mt < 4; mt++)
#pragma unroll
        for (int nt = 0; nt < 4; nt++)
#pragma unroll
            for (int i = 0; i < 4; i++) acc[mt][nt][i] = 0.0f;

    // prologue: fill stages 0, 1 (prefetch distance 2)
    load_stage(0);
    CP_COMMIT();
    load_stage(1);
    CP_COMMIT();

    int s = 0;                         // current stage, wraps mod 3
    int sload = 2;                     // stage to load next, wraps mod 3
#pragma unroll 1
    for (int ch = 0; ch < NCH; ch++) {
        CP_WAIT1();
        __syncthreads();               // single barrier: also guards stage reuse
        if (ch + 2 < NCH) load_stage(sload);
        CP_COMMIT();   // unconditional: keeps wait_group bookkeeping exact

        const uint32_t sa = sbase + (uint32_t)s * (A_STAGE * 2);
        const uint32_t sb = sbase + (uint32_t)(B_BASE * 2 + s * (B_STAGE * 2));
#pragma unroll
        for (int ks = 0; ks < 2; ks++) {
            // ---- A fragments: hi/lo x 4 m-tiles via ldmatrix.x4 ----
            uint32_t ah[4][4], al[4][4];
            {
                const int m_local = wm * 64 + (quad & 1) * 8 + r8;
                const int k_off = ks * 16 + (quad >> 1) * 8;
                const uint32_t abase = sa +
                    (uint32_t)(m_local * A_STRIDE + k_off) * 2;
#pragma unroll
                for (int mt = 0; mt < 4; mt++) {
                    ldsm4(ah[mt], abase + (uint32_t)(mt * 16 * A_STRIDE) * 2);
                    ldsm4(al[mt], abase + (uint32_t)(A_PLANE + mt * 16 * A_STRIDE) * 2);
                }
            }
            // ---- B fragments per 16-col group; term-major MMA ordering ----
            {
                const int k_row = ks * 16 + (quad & 1) * 8 + r8;
                const int n_col = wn * 32 + (quad >> 1) * 8;
                const uint32_t bbase = sb +
                    (uint32_t)(k_row * B_STRIDE + n_col) * 2;
#pragma unroll
                for (int nt2 = 0; nt2 < 2; nt2++) {
                    uint32_t bh[4], bl[4];
                    ldsm4t(bh, bbase + (uint32_t)(nt2 * 16) * 2);
                    ldsm4t(bl, bbase + (uint32_t)(B_PLANE + nt2 * 16) * 2);
                    const int nt = nt2 * 2;
                    // term 1: hi*hi  (8 independent accumulators in a row)
#pragma unroll
                    for (int mt = 0; mt < 4; mt++) {
                        mma_bf16(acc[mt][nt],     ah[mt], bh);
                        mma_bf16(acc[mt][nt + 1], ah[mt], bh + 2);
                    }
                    // term 2: lo*hi
#pragma unroll
                    for (int mt = 0; mt < 4; mt++) {
                        mma_bf16(acc[mt][nt],     al[mt], bh);
                        mma_bf16(acc[mt][nt + 1], al[mt], bh + 2);
                    }
                    // term 3: hi*lo
#pragma unroll
                    for (int mt = 0; mt < 4; mt++) {
                        mma_bf16(acc[mt][nt],     ah[mt], bl);
                        mma_bf16(acc[mt][nt + 1], ah[mt], bl + 2);
                    }
                }
            }
        }
        s = (s == 2) ? 0 : s + 1;
        sload = (sload == 2) ? 0 : sload + 1;
    }

    // ---------------- epilogue -----------------------------------------------
#pragma unroll
    for (int mt = 0; mt < 4; mt++) {
        const int lm0 = wm * 64 + mt * 16 + r;       // local row of acc[0],acc[1]
        const int lm1 = lm0 + 8;                     // local row of acc[2],acc[3]
#pragma unroll
        for (int nt = 0; nt < 4; nt++) {
            const int bcol = n0 + wn * 32 + nt * 8 + c * 2;
            const float bb0 = bias_en ? bias[e * Nld + bcol] : 0.0f;
            const float bb1 = bias_en ? bias[e * Nld + bcol + 1] : 0.0f;
            if (GELU_EPI) {
                float v00 = gelu_f(acc[mt][nt][0] + bb0);
                float v01 = gelu_f(acc[mt][nt][1] + bb1);
                float v10 = gelu_f(acc[mt][nt][2] + bb0);
                float v11 = gelu_f(acc[mt][nt][3] + bb1);
                __nv_bfloat162 h0, h1, l0, l1;
                h0.x = __float2bfloat16_rn(v00);
                h0.y = __float2bfloat16_rn(v01);
                h1.x = __float2bfloat16_rn(v10);
                h1.y = __float2bfloat16_rn(v11);
                l0.x = __float2bfloat16_rn(v00 - __bfloat162float(h0.x));
                l0.y = __float2bfloat16_rn(v01 - __bfloat162float(h0.y));
                l1.x = __float2bfloat16_rn(v10 - __bfloat162float(h1.x));
                l1.y = __float2bfloat16_rn(v11 - __bfloat162float(h1.y));
                *(__nv_bfloat162*)(outbh + (size_t)(m0 + lm0) * Nld + bcol) = h0;
                *(__nv_bfloat162*)(outbh + (size_t)(m0 + lm1) * Nld + bcol) = h1;
                *(__nv_bfloat162*)(outbl + (size_t)(m0 + lm0) * Nld + bcol) = l0;
                *(__nv_bfloat162*)(outbl + (size_t)(m0 + lm1) * Nld + bcol) = l1;
            } else {
                const float w0 = val_s[lm0];
                const float w1 = val_s[lm1];
                float* p0 = outa + (size_t)tok_s[lm0] * ND + bcol;
                float* p1 = outa + (size_t)tok_s[lm1] * ND + bcol;
                red_v2(p0, (acc[mt][nt][0] + bb0) * w0, (acc[mt][nt][1] + bb1) * w0);
                red_v2(p1, (acc[mt][nt][2] + bb0) * w1, (acc[mt][nt][3] + bb1) * w1);
            }
        }
    }
}

// ============================ host launch =====================================
extern "C" void kernel_launch(void* const* d_in, const int* in_sizes, int n_in,
                              void* d_out, int out_size) {
    const float* x  = (const float*)d_in[0];   // [T, D]
    const float* Wg = (const float*)d_in[1];   // [D, E]
    const float* W1 = (const float*)d_in[2];   // [E, D, F]
    const float* b1 = (const float*)d_in[3];   // [E, F]
    const float* W2 = (const float*)d_in[4];   // [E, F, D]
    const float* b2 = (const float*)d_in[5];   // [E, D]
    float* out = (float*)d_out;

    void *p_xh, *p_xl, *p_w1h, *p_w1l, *p_w2h, *p_w2l, *p_hh, *p_hl;
    cudaGetSymbolAddress(&p_xh, g_xh);
    cudaGetSymbolAddress(&p_xl, g_xl);
    cudaGetSymbolAddress(&p_w1h, g_w1h);
    cudaGetSymbolAddress(&p_w1l, g_w1l);
    cudaGetSymbolAddress(&p_w2h, g_w2h);
    cudaGetSymbolAddress(&p_w2l, g_w2l);
    cudaGetSymbolAddress(&p_hh, g_hh);
    cudaGetSymbolAddress(&p_hl, g_hl);

    cudaFuncSetAttribute((const void*)gemm_tc_kernel<32, true, true>,
                         cudaFuncAttributeMaxDynamicSharedMemorySize,
                         GEMM_SMEM_BYTES);
    cudaFuncSetAttribute((const void*)gemm_tc_kernel<64, false, false>,
                         cudaFuncAttributeMaxDynamicSharedMemorySize,
                         GEMM_SMEM_BYTES);

    size_t n_main = (size_t)NT * ND;
    init_out_kernel<<<512, 256>>>(out, n_main, (size_t)out_size);
    router_kernel<<<NT / 32, 1024>>>(x, Wg);
    topk_kernel<<<NE, 1024>>>();

    // Pre-split operands into bf16 hi/lo planes, 8 floats/thread.
    split_kernel<<<(NT * ND / 8 + 255) / 256, 256>>>(
        (const float4*)x, (uint4*)p_xh, (uint4*)p_xl, (size_t)NT * ND / 8);
    split_kernel<<<((size_t)NE * ND * NF / 8 + 255) / 256, 256>>>(
        (const float4*)W1, (uint4*)p_w1h, (uint4*)p_w1l,
        (size_t)NE * ND * NF / 8);
    split_kernel<<<((size_t)NE * NF * ND / 8 + 255) / 256, 256>>>(
        (const float4*)W2, (uint4*)p_w2h, (uint4*)p_w2l,
        (size_t)NE * NF * ND / 8);

    // GEMM1: h = gelu(x[idx] @ W1[e] + b1[e])   M=16384, N=4096, K=1024
    gemm_tc_kernel<32, true, true>
        <<<dim3(NF / 128, NM / 128, 1), 256, GEMM_SMEM_BYTES>>>(
            (const __nv_bfloat16*)p_xh, (const __nv_bfloat16*)p_xl,
            (const __nv_bfloat16*)p_w1h, (const __nv_bfloat16*)p_w1l,
            b1, nullptr,
            (__nv_bfloat16*)p_hh, (__nv_bfloat16*)p_hl, NF, ND, ND);

    // GEMM2: out[tok] += val*(h @ W2[e] + b2[e])  M=16384, N=1024, K=4096
    // split-K = 2 (epilogue is scatter-add, so K-slices both reduce in)
    gemm_tc_kernel<64, false, false>
        <<<dim3(ND / 128, NM / 128, 2), 256, GEMM_SMEM_BYTES>>>(
            (const __nv_bfloat16*)p_hh, (const __nv_bfloat16*)p_hl,
            (const __nv_bfloat16*)p_w2h, (const __nv_bfloat16*)p_w2l,
            b2, out, nullptr, nullptr, ND, NF, NF);
}

// round 13
// speedup vs baseline: 1.2022x; 1.1084x over previous
#include <cuda_runtime.h>
#include <cuda_bf16.h>
#include <cuda_fp16.h>
#include <cstdint>

// Problem constants
#define NE 8
#define ND 1024
#define NF 4096
#define NT 8192
#define NC 2048
#define NM (NE * NC)   // 16384 rows through the expert FFN

// ---------------- scratch (device globals; no runtime allocation) ----------
__device__ float g_scoresT[NE * NT];              // gates^T  [E, T]
__device__ int   g_idx[NM];                       // selected token ids [E*C]
__device__ float g_vals[NM];                      // routing probs of selected
__device__ __nv_bfloat16 g_xh[(size_t)NT * ND];   // x split hi (bf16)
__device__ __nv_bfloat16 g_xl[(size_t)NT * ND];   // x split lo (bf16)
__device__ __nv_bfloat16 g_w1h[(size_t)NE * ND * NF];
__device__ __nv_bfloat16 g_w1l[(size_t)NE * ND * NF];
__device__ __half g_w2h[(size_t)NE * NF * ND];    // W2 fp16 hi plane only
__device__ __half g_hh[(size_t)NM * NF];          // gelu output fp16 hi
__device__ __half g_hl[(size_t)NM * NF];          // gelu output fp16 lo

// ---------------- init output ------------------------------------------------
__global__ void init_out_kernel(float* out, size_t n_main, size_t total) {
    size_t i = (size_t)blockIdx.x * blockDim.x + threadIdx.x;
    size_t stride = (size_t)gridDim.x * blockDim.x;
    for (; i < total; i += stride) {
        if (i < n_main)       out[i] = 0.0f;
        else if (i == n_main) out[i] = 2.0f;   // aux_loss = E*(C/T)*1 = 2 analytically
        else                  out[i] = 0.0f;
    }
}

// ---------------- fp32 -> (hi, lo) bf16 split, 8 floats/thread --------------
__global__ void split_kernel(const float4* __restrict__ in,
                             uint4* __restrict__ hi,
                             uint4* __restrict__ lo, size_t n8) {
    size_t i = (size_t)blockIdx.x * blockDim.x + threadIdx.x;
    if (i >= n8) return;
    float4 a = in[2 * i];
    float4 b = in[2 * i + 1];
    __nv_bfloat162 h[4], l[4];
    h[0] = __floats2bfloat162_rn(a.x, a.y);
    h[1] = __floats2bfloat162_rn(a.z, a.w);
    h[2] = __floats2bfloat162_rn(b.x, b.y);
    h[3] = __floats2bfloat162_rn(b.z, b.w);
    l[0] = __floats2bfloat162_rn(a.x - __bfloat162float(h[0].x),
                                 a.y - __bfloat162float(h[0].y));
    l[1] = __floats2bfloat162_rn(a.z - __bfloat162float(h[1].x),
                                 a.w - __bfloat162float(h[1].y));
    l[2] = __floats2bfloat162_rn(b.x - __bfloat162float(h[2].x),
                                 b.y - __bfloat162float(h[2].y));
    l[3] = __floats2bfloat162_rn(b.z - __bfloat162float(h[3].x),
                                 b.w - __bfloat162float(h[3].y));
    hi[i] = *(const uint4*)h;
    lo[i] = *(const uint4*)l;
}

// ---------------- fp32 -> fp16 hi-only convert, 8 floats/thread -------------
__global__ void cvt_f16_kernel(const float4* __restrict__ in,
                               uint4* __restrict__ hi, size_t n8) {
    size_t i = (size_t)blockIdx.x * blockDim.x + threadIdx.x;
    if (i >= n8) return;
    float4 a = in[2 * i];
    float4 b = in[2 * i + 1];
    __half2 h[4];
    h[0] = __floats2half2_rn(a.x, a.y);
    h[1] = __floats2half2_rn(a.z, a.w);
    h[2] = __floats2half2_rn(b.x, b.y);
    h[3] = __floats2half2_rn(b.z, b.w);
    hi[i] = *(const uint4*)h;
}

// ---------------- router: gates = softmax(x @ Wg), stored transposed --------
__global__ void router_kernel(const float* __restrict__ x,
                              const float* __restrict__ Wg) {
    int warp = (blockIdx.x * blockDim.x + threadIdx.x) >> 5;
    int lane = threadIdx.x & 31;
    if (warp >= NT) return;
    const float* xr = x + (size_t)warp * ND;
    float acc[NE];
#pragma unroll
    for (int e = 0; e < NE; e++) acc[e] = 0.0f;
    for (int d = lane; d < ND; d += 32) {
        float xv = xr[d];
        const float4 w0 = *(const float4*)(Wg + d * NE);
        const float4 w1 = *(const float4*)(Wg + d * NE + 4);
        acc[0] += xv * w0.x; acc[1] += xv * w0.y;
        acc[2] += xv * w0.z; acc[3] += xv * w0.w;
        acc[4] += xv * w1.x; acc[5] += xv * w1.y;
        acc[6] += xv * w1.z; acc[7] += xv * w1.w;
    }
#pragma unroll
    for (int off = 16; off > 0; off >>= 1) {
#pragma unroll
        for (int e = 0; e < NE; e++)
            acc[e] += __shfl_down_sync(0xffffffffu, acc[e], off);
    }
    if (lane == 0) {
        float m = acc[0];
#pragma unroll
        for (int e = 1; e < NE; e++) m = fmaxf(m, acc[e]);
        float s = 0.0f;
#pragma unroll
        for (int e = 0; e < NE; e++) { acc[e] = expf(acc[e] - m); s += acc[e]; }
        float inv = 1.0f / s;
#pragma unroll
        for (int e = 0; e < NE; e++) g_scoresT[e * NT + warp] = acc[e] * inv;
    }
}

// ---------------- exact top-C per expert via 4-pass radix select ------------
__global__ void topk_kernel() {
    int e = blockIdx.x;
    int tid = threadIdx.x;
    const float* s = g_scoresT + e * NT;

    __shared__ unsigned hist[256];
    __shared__ unsigned sh_prefix;
    __shared__ int sh_rem;

    unsigned prefix = 0;
    int remaining = NC;

    for (int shift = 24; shift >= 0; shift -= 8) {
        if (tid < 256) hist[tid] = 0;
        __syncthreads();
        unsigned mask = (shift == 24) ? 0u : (0xFFFFFFFFu << (shift + 8));
        for (int t = tid; t < NT; t += blockDim.x) {
            unsigned k = __float_as_uint(s[t]);
            if ((k & mask) == prefix) atomicAdd(&hist[(k >> shift) & 0xFFu], 1u);
        }
        __syncthreads();
        if (tid == 0) {
            int rem = remaining;
            int b = 0;
            for (int d = 255; d >= 0; d--) {
                int h = (int)hist[d];
                if (h >= rem) { b = d; break; }
                rem -= h;
            }
            sh_prefix = prefix | ((unsigned)b << shift);
            sh_rem = rem;
        }
        __syncthreads();
        prefix = sh_prefix;
        remaining = sh_rem;
        __syncthreads();
    }

    __shared__ int cnt_gt, cnt_eq;
    if (tid == 0) { cnt_gt = 0; cnt_eq = 0; }
    __syncthreads();
    int base = NC - remaining;
    for (int t = tid; t < NT; t += blockDim.x) {
        unsigned k = __float_as_uint(s[t]);
        if (k > prefix) {
            int p = atomicAdd(&cnt_gt, 1);
            g_idx[e * NC + p]  = t;
            g_vals[e * NC + p] = s[t];
        } else if (k == prefix) {
            int p = atomicAdd(&cnt_eq, 1);
            if (p < remaining) {
                g_idx[e * NC + base + p]  = t;
                g_vals[e * NC + base + p] = s[t];
            }
        }
    }
}

// ---------------- gelu (tanh approx via fast exp; matches jax to ~1e-6) -----
__device__ __forceinline__ float gelu_f(float v) {
    float u = 0.7978845608028654f * (v + 0.044715f * v * v * v);
    float t = 1.0f - 2.0f / (__expf(2.0f * u) + 1.0f);
    return 0.5f * v * (1.0f + t);
}

// ============================ split mma.sync GEMM =============================
// CTA tile 128(M) x 128(N) x 32(K). 256 threads, 8 warps 2(m) x 4(n),
// warp tile 64x32. 3-stage cp.async pipeline, single top barrier, 2 CTAs/SM.
// MODE bf16 (F16_2T=false): hi*hi + lo*hi + hi*lo, bf16 operands, f32 accum.
// MODE f16  (F16_2T=true) : (a_hi + a_lo exact fp16 split) * b_hi, 2 MMAs,
//                           f16 operands, f32 accum. B lo plane unused.

static constexpr int A_STRIDE = 40;                 // 16-bit units (80 B)
static constexpr int A_PLANE  = 128 * A_STRIDE;     // 5120
static constexpr int A_STAGE  = 2 * A_PLANE;        // hi + lo = 10240
static constexpr int B_BASE   = 3 * A_STAGE;        // 30720
static constexpr int B_STRIDE = 136;                // 16-bit units (272 B, 17*16)
static constexpr int B_PLANE  = 32 * B_STRIDE;      // 4352
static constexpr int B_STAGE  = 2 * B_PLANE;        // 8704
static constexpr int SMEM_U16 = B_BASE + 3 * B_STAGE;        // 56832
static constexpr int GEMM_SMEM_BYTES = SMEM_U16 * 2;         // 113664

__device__ __forceinline__ uint32_t smem_u32(const void* p) {
    uint32_t a;
    asm("{ .reg .u64 t; cvta.to.shared.u64 t, %1; cvt.u32.u64 %0, t; }"
        : "=r"(a) : "l"(p));
    return a;
}

__device__ __forceinline__ void cp16(uint32_t dst, const void* src) {
    asm volatile("cp.async.cg.shared.global [%0], [%1], 16;"
                 :: "r"(dst), "l"(src) : "memory");
}
#define CP_COMMIT() asm volatile("cp.async.commit_group;" ::: "memory")
#define CP_WAIT1()  asm volatile("cp.async.wait_group 1;" ::: "memory")

__device__ __forceinline__ void ldsm4(uint32_t* r, uint32_t addr) {
    asm volatile("ldmatrix.sync.aligned.m8n8.x4.shared.b16 {%0,%1,%2,%3}, [%4];"
                 : "=r"(r[0]), "=r"(r[1]), "=r"(r[2]), "=r"(r[3]) : "r"(addr));
}
__device__ __forceinline__ void ldsm4t(uint32_t* r, uint32_t addr) {
    asm volatile("ldmatrix.sync.aligned.m8n8.x4.trans.shared.b16 {%0,%1,%2,%3}, [%4];"
                 : "=r"(r[0]), "=r"(r[1]), "=r"(r[2]), "=r"(r[3]) : "r"(addr));
}

__device__ __forceinline__ void mma_bf16(float* d, const uint32_t* a,
                                         const uint32_t* b) {
    asm volatile(
        "mma.sync.aligned.m16n8k16.row.col.f32.bf16.bf16.f32 "
        "{%0,%1,%2,%3}, {%4,%5,%6,%7}, {%8,%9}, {%0,%1,%2,%3};"
        : "+f"(d[0]), "+f"(d[1]), "+f"(d[2]), "+f"(d[3])
        : "r"(a[0]), "r"(a[1]), "r"(a[2]), "r"(a[3]), "r"(b[0]), "r"(b[1]));
}
__device__ __forceinline__ void mma_f16(float* d, const uint32_t* a,
                                        const uint32_t* b) {
    asm volatile(
        "mma.sync.aligned.m16n8k16.row.col.f32.f16.f16.f32 "
        "{%0,%1,%2,%3}, {%4,%5,%6,%7}, {%8,%9}, {%0,%1,%2,%3};"
        : "+f"(d[0]), "+f"(d[1]), "+f"(d[2]), "+f"(d[3])
        : "r"(a[0]), "r"(a[1]), "r"(a[2]), "r"(a[3]), "r"(b[0]), "r"(b[1]));
}

__device__ __forceinline__ void red_v2(float* ptr, float v0, float v1) {
    asm volatile("red.global.add.v2.f32 [%0], {%1, %2};"
                 :: "l"(ptr), "f"(v0), "f"(v1) : "memory");
}

// NCH chunks of K=32 per CTA per K-slice. GATHER: A rows via g_idx (lda=ND).
// GELU_EPI: write fp16-split gelu(acc+bias); else scatter-add into fp32 outa.
// F16_2T: fp16 operands, 2 MMA terms (B lo plane absent).
// blockIdx.z = K-slice; slice 0 adds bias. Ktot = full K (B expert stride).
template<int NCH, bool GATHER, bool GELU_EPI, bool F16_2T>
__global__ __launch_bounds__(256, 2) void gemm_tc_kernel(
    const uint16_t* __restrict__ Ah,
    const uint16_t* __restrict__ Al,
    const uint16_t* __restrict__ Bh,
    const uint16_t* __restrict__ Bl,       // unused when F16_2T
    const float* __restrict__ bias,
    float* __restrict__ outa,
    __half* __restrict__ outbh,
    __half* __restrict__ outbl,
    int Nld, int lda, int Ktot) {
    extern __shared__ __align__(16) uint16_t sm[];
    __shared__ int   tok_s[128];
    __shared__ float val_s[128];

    constexpr int BPL = F16_2T ? 1 : 2;    // B planes
    constexpr int BJ  = 2 * BPL;           // B cp16 per thread per stage

    const int tid = threadIdx.x;
    const int warp = tid >> 5;
    const int lane = tid & 31;
    const int wm = warp >> 2;          // 0..1  (64-row slab)
    const int wn = warp & 3;           // 0..3  (32-col slab)
    const int r = lane >> 2;           // 0..7 (accumulator row)
    const int c = lane & 3;            // 0..3 (accumulator col pair)
    const int quad = lane >> 3;        // 0..3 (ldmatrix matrix id)
    const int r8 = lane & 7;           // row within 8x8 matrix

    const int n0 = blockIdx.x * 128;
    const int m0 = blockIdx.y * 128;
    const int e = m0 >> 11;            // m0 / NC
    const int kbase = blockIdx.z * NCH * 32;
    const bool bias_en = (blockIdx.z == 0);

    if (tid < 128) {
        tok_s[tid] = g_idx[m0 + tid];
        val_s[tid] = g_vals[m0 + tid];
    }
    __syncthreads();

    const uint32_t sbase = smem_u32(sm);

    // ---- precomputed load pointers (advance one K-chunk per load_stage) ----
    const uint16_t* asrc[4];           // 2 planes x 2 iterations (A: 512 cp16)
    uint32_t adst0[4];
    const uint16_t* bsrc[4];           // BPL planes x 2 iterations
    uint32_t bdst0[4];
    {
        const uint16_t* aps[2] = {Ah, Al};
        const size_t bexp = (size_t)e * Ktot * Nld + n0;
        const uint16_t* bps[2] = {Bh + bexp, F16_2T ? nullptr : (Bl + bexp)};
#pragma unroll
        for (int p = 0; p < 2; p++) {
#pragma unroll
            for (int i = 0; i < 2; i++) {          // A: 128 rows x 4 segs
                int lin = tid + 256 * i;
                int row = lin >> 2;
                int seg = (lin & 3) * 8;
                int j = p * 2 + i;
                asrc[j] = GATHER
                    ? (aps[p] + (size_t)tok_s[row] * lda + kbase + seg)
                    : (aps[p] + (size_t)(m0 + row) * lda + kbase + seg);
                adst0[j] = sbase + (uint32_t)(p * A_PLANE + row * A_STRIDE + seg) * 2;
            }
        }
#pragma unroll
        for (int p = 0; p < BPL; p++) {
#pragma unroll
            for (int i = 0; i < 2; i++) {          // B: 32 rows x 16 segs
                int lin = tid + 256 * i;
                int row = lin >> 4;                // 0..31
                int seg = (lin & 15) * 8;
                int j = p * 2 + i;
                bsrc[j] = bps[p] + (size_t)(kbase + row) * Nld + seg;
                bdst0[j] = sbase + (uint32_t)(B_BASE + p * B_PLANE +
                                              row * B_STRIDE + seg) * 2;
            }
        }
    }

    auto load_stage = [&](int s) {
        const uint32_t ao = (uint32_t)s * (A_STAGE * 2);
        const uint32_t bo = (uint32_t)s * (B_STAGE * 2);
#pragma unroll
        for (int j = 0; j < 4; j++) {
            cp16(adst0[j] + ao, asrc[j]);
            asrc[j] += 32;
        }
#pragma unroll
        for (int j = 0; j < BJ; j++) {
            cp16(bdst0[j] + bo, bsrc[j]);
            bsrc[j] += (size_t)32 * Nld;
        }
    };

    float acc[4][4][4];                // [mt][nt][frag]
#pragma unroll
    for (int mt = 0; mt < 4; mt++)
#pragma unroll
        for (int nt = 0; nt < 4; nt++)
#pragma unroll
            for (int i = 0; i < 4; i++) acc[mt][nt][i] = 0.0f;

    // prologue: fill stages 0, 1 (prefetch distance 2)
    load_stage(0);
    CP_COMMIT();
    load_stage(1);
    CP_COMMIT();

    int s = 0;                         // current stage, wraps mod 3
    int sload = 2;                     // stage to load next, wraps mod 3
#pragma unroll 1
    for (int ch = 0; ch < NCH; ch++) {
        CP_WAIT1();
        __syncthreads();               // single barrier: also guards stage reuse
        if (ch + 2 < NCH) load_stage(sload);
        CP_COMMIT();   // unconditional: keeps wait_group bookkeeping exact

        const uint32_t sa = sbase + (uint32_t)s * (A_STAGE * 2);
        const uint32_t sb = sbase + (uint32_t)(B_BASE * 2 + s * (B_STAGE * 2));
#pragma unroll
        for (int ks = 0; ks < 2; ks++) {
            // ---- A fragments: hi/lo x 4 m-tiles via ldmatrix.x4 ----
            uint32_t ah[4][4], al[4][4];
            {
                const int m_local = wm * 64 + (quad & 1) * 8 + r8;
                const int k_off = ks * 16 + (quad >> 1) * 8;
                const uint32_t abase = sa +
                    (uint32_t)(m_local * A_STRIDE + k_off) * 2;
#pragma unroll
                for (int mt = 0; mt < 4; mt++) {
                    ldsm4(ah[mt], abase + (uint32_t)(mt * 16 * A_STRIDE) * 2);
                    ldsm4(al[mt], abase + (uint32_t)(A_PLANE + mt * 16 * A_STRIDE) * 2);
                }
            }
            // ---- B fragments per 16-col group; term-major MMA ordering ----
            {
                const int k_row = ks * 16 + (quad & 1) * 8 + r8;
                const int n_col = wn * 32 + (quad >> 1) * 8;
                const uint32_t bbase = sb +
                    (uint32_t)(k_row * B_STRIDE + n_col) * 2;
#pragma unroll
                for (int nt2 = 0; nt2 < 2; nt2++) {
                    uint32_t bh[4];
                    ldsm4t(bh, bbase + (uint32_t)(nt2 * 16) * 2);
                    const int nt = nt2 * 2;
                    if (F16_2T) {
                        // a_hi*b_hi + a_lo*b_hi  (= full-precision A times b_hi)
#pragma unroll
                        for (int mt = 0; mt < 4; mt++) {
                            mma_f16(acc[mt][nt],     ah[mt], bh);
                            mma_f16(acc[mt][nt + 1], ah[mt], bh + 2);
                        }
#pragma unroll
                        for (int mt = 0; mt < 4; mt++) {
                            mma_f16(acc[mt][nt],     al[mt], bh);
                            mma_f16(acc[mt][nt + 1], al[mt], bh + 2);
                        }
                    } else {
                        uint32_t bl[4];
                        ldsm4t(bl, bbase + (uint32_t)(B_PLANE + nt2 * 16) * 2);
                        // term 1: hi*hi
#pragma unroll
                        for (int mt = 0; mt < 4; mt++) {
                            mma_bf16(acc[mt][nt],     ah[mt], bh);
                            mma_bf16(acc[mt][nt + 1], ah[mt], bh + 2);
                        }
                        // term 2: lo*hi
#pragma unroll
                        for (int mt = 0; mt < 4; mt++) {
                            mma_bf16(acc[mt][nt],     al[mt], bh);
                            mma_bf16(acc[mt][nt + 1], al[mt], bh + 2);
                        }
                        // term 3: hi*lo
#pragma unroll
                        for (int mt = 0; mt < 4; mt++) {
                            mma_bf16(acc[mt][nt],     ah[mt], bl);
                            mma_bf16(acc[mt][nt + 1], ah[mt], bl + 2);
                        }
                    }
                }
            }
        }
        s = (s == 2) ? 0 : s + 1;
        sload = (sload == 2) ? 0 : sload + 1;
    }

    // ---------------- epilogue -----------------------------------------------
#pragma unroll
    for (int mt = 0; mt < 4; mt++) {
        const int lm0 = wm * 64 + mt * 16 + r;       // local row of acc[0],acc[1]
        const int lm1 = lm0 + 8;                     // local row of acc[2],acc[3]
#pragma unroll
        for (int nt = 0; nt < 4; nt++) {
            const int bcol = n0 + wn * 32 + nt * 8 + c * 2;
            const float bb0 = bias_en ? bias[e * Nld + bcol] : 0.0f;
            const float bb1 = bias_en ? bias[e * Nld + bcol + 1] : 0.0f;
            if (GELU_EPI) {
                float v00 = gelu_f(acc[mt][nt][0] + bb0);
                float v01 = gelu_f(acc[mt][nt][1] + bb1);
                float v10 = gelu_f(acc[mt][nt][2] + bb0);
                float v11 = gelu_f(acc[mt][nt][3] + bb1);
                __half h00 = __float2half_rn(v00);
                __half h01 = __float2half_rn(v01);
                __half h10 = __float2half_rn(v10);
                __half h11 = __float2half_rn(v11);
                __half2 hp0 = __halves2half2(h00, h01);
                __half2 hp1 = __halves2half2(h10, h11);
                __half2 lp0 = __floats2half2_rn(v00 - __half2float(h00),
                                                v01 - __half2float(h01));
                __half2 lp1 = __floats2half2_rn(v10 - __half2float(h10),
                                                v11 - __half2float(h11));
                *(__half2*)(outbh + (size_t)(m0 + lm0) * Nld + bcol) = hp0;
                *(__half2*)(outbh + (size_t)(m0 + lm1) * Nld + bcol) = hp1;
                *(__half2*)(outbl + (size_t)(m0 + lm0) * Nld + bcol) = lp0;
                *(__half2*)(outbl + (size_t)(m0 + lm1) * Nld + bcol) = lp1;
            } else {
                const float w0 = val_s[lm0];
                const float w1 = val_s[lm1];
                float* p0 = outa + (size_t)tok_s[lm0] * ND + bcol;
                float* p1 = outa + (size_t)tok_s[lm1] * ND + bcol;
                red_v2(p0, (acc[mt][nt][0] + bb0) * w0, (acc[mt][nt][1] + bb1) * w0);
                red_v2(p1, (acc[mt][nt][2] + bb0) * w1, (acc[mt][nt][3] + bb1) * w1);
            }
        }
    }
}

// ============================ host launch =====================================
extern "C" void kernel_launch(void* const* d_in, const int* in_sizes, int n_in,
                              void* d_out, int out_size) {
    const float* x  = (const float*)d_in[0];   // [T, D]
    const float* Wg = (const float*)d_in[1];   // [D, E]
    const float* W1 = (const float*)d_in[2];   // [E, D, F]
    const float* b1 = (const float*)d_in[3];   // [E, F]
    const float* W2 = (const float*)d_in[4];   // [E, F, D]
    const float* b2 = (const float*)d_in[5];   // [E, D]
    float* out = (float*)d_out;

    void *p_xh, *p_xl, *p_w1h, *p_w1l, *p_w2h, *p_hh, *p_hl;
    cudaGetSymbolAddress(&p_xh, g_xh);
    cudaGetSymbolAddress(&p_xl, g_xl);
    cudaGetSymbolAddress(&p_w1h, g_w1h);
    cudaGetSymbolAddress(&p_w1l, g_w1l);
    cudaGetSymbolAddress(&p_w2h, g_w2h);
    cudaGetSymbolAddress(&p_hh, g_hh);
    cudaGetSymbolAddress(&p_hl, g_hl);

    cudaFuncSetAttribute(
        (const void*)gemm_tc_kernel<32, true, true, false>,
        cudaFuncAttributeMaxDynamicSharedMemorySize, GEMM_SMEM_BYTES);
    cudaFuncSetAttribute(
        (const void*)gemm_tc_kernel<64, false, false, true>,
        cudaFuncAttributeMaxDynamicSharedMemorySize, GEMM_SMEM_BYTES);

    size_t n_main = (size_t)NT * ND;
    init_out_kernel<<<512, 256>>>(out, n_main, (size_t)out_size);
    router_kernel<<<NT / 32, 1024>>>(x, Wg);
    topk_kernel<<<NE, 1024>>>();

    // Pre-split operands: x, W1 -> bf16 hi/lo planes; W2 -> fp16 hi only.
    split_kernel<<<(NT * ND / 8 + 255) / 256, 256>>>(
        (const float4*)x, (uint4*)p_xh, (uint4*)p_xl, (size_t)NT * ND / 8);
    split_kernel<<<((size_t)NE * ND * NF / 8 + 255) / 256, 256>>>(
        (const float4*)W1, (uint4*)p_w1h, (uint4*)p_w1l,
        (size_t)NE * ND * NF / 8);
    cvt_f16_kernel<<<((size_t)NE * NF * ND / 8 + 255) / 256, 256>>>(
        (const float4*)W2, (uint4*)p_w2h, (size_t)NE * NF * ND / 8);

    // GEMM1: h = gelu(x[idx] @ W1[e] + b1[e])   bf16 3-term
    gemm_tc_kernel<32, true, true, false>
        <<<dim3(NF / 128, NM / 128, 1), 256, GEMM_SMEM_BYTES>>>(
            (const uint16_t*)p_xh, (const uint16_t*)p_xl,
            (const uint16_t*)p_w1h, (const uint16_t*)p_w1l,
            b1, nullptr,
            (__half*)p_hh, (__half*)p_hl, NF, ND, ND);

    // GEMM2: out[tok] += val*(h @ W2[e] + b2[e])   fp16 2-term, split-K = 2
    gemm_tc_kernel<64, false, false, true>
        <<<dim3(ND / 128, NM / 128, 2), 256, GEMM_SMEM_BYTES>>>(
            (const uint16_t*)p_hh, (const uint16_t*)p_hl,
            (const uint16_t*)p_w2h, nullptr,
            b2, out, nullptr, nullptr, ND, NF, NF);
}

// round 14
// speedup vs baseline: 1.3859x; 1.1527x over previous
#include <cuda_runtime.h>
#include <cuda_bf16.h>
#include <cuda_fp16.h>
#include <cstdint>

// Problem constants
#define NE 8
#define ND 1024
#define NF 4096
#define NT 8192
#define NC 2048
#define NM (NE * NC)   // 16384 rows through the expert FFN

// ---------------- scratch (device globals; no runtime allocation) ----------
__device__ float g_scoresT[NE * NT];              // gates^T  [E, T]
__device__ int   g_idx[NM];                       // selected token ids [E*C]
__device__ float g_vals[NM];                      // routing probs of selected
__device__ __half g_xh[(size_t)NT * ND];          // x fp16 hi
__device__ __half g_xl[(size_t)NT * ND];          // x fp16 lo (exact residual)
__device__ __half g_w1h[(size_t)NE * ND * NF];    // W1 fp16 hi only
__device__ __half g_w2h[(size_t)NE * NF * ND];    // W2 fp16 hi only
__device__ __half g_hh[(size_t)NM * NF];          // gelu output fp16 hi
__device__ __half g_hl[(size_t)NM * NF];          // gelu output fp16 lo

// ---------------- init output ------------------------------------------------
__global__ void init_out_kernel(float* out, size_t n_main, size_t total) {
    size_t i = (size_t)blockIdx.x * blockDim.x + threadIdx.x;
    size_t stride = (size_t)gridDim.x * blockDim.x;
    for (; i < total; i += stride) {
        if (i < n_main)       out[i] = 0.0f;
        else if (i == n_main) out[i] = 2.0f;   // aux_loss = E*(C/T)*1 = 2 analytically
        else                  out[i] = 0.0f;
    }
}

// ------------- fp32 -> (hi, lo) fp16 split, 8 floats/thread -----------------
__global__ void split_f16_kernel(const float4* __restrict__ in,
                                 uint4* __restrict__ hi,
                                 uint4* __restrict__ lo, size_t n8) {
    size_t i = (size_t)blockIdx.x * blockDim.x + threadIdx.x;
    if (i >= n8) return;
    float4 a = in[2 * i];
    float4 b = in[2 * i + 1];
    float v[8] = {a.x, a.y, a.z, a.w, b.x, b.y, b.z, b.w};
    __half2 h[4], l[4];
#pragma unroll
    for (int j = 0; j < 4; j++) {
        float v0 = v[2 * j], v1 = v[2 * j + 1];
        __half h0 = __float2half_rn(v0);
        __half h1 = __float2half_rn(v1);
        h[j] = __halves2half2(h0, h1);
        l[j] = __floats2half2_rn(v0 - __half2float(h0),
                                 v1 - __half2float(h1));
    }
    hi[i] = *(const uint4*)h;
    lo[i] = *(const uint4*)l;
}

// ---------------- fp32 -> fp16 hi-only convert, 8 floats/thread -------------
__global__ void cvt_f16_kernel(const float4* __restrict__ in,
                               uint4* __restrict__ hi, size_t n8) {
    size_t i = (size_t)blockIdx.x * blockDim.x + threadIdx.x;
    if (i >= n8) return;
    float4 a = in[2 * i];
    float4 b = in[2 * i + 1];
    __half2 h[4];
    h[0] = __floats2half2_rn(a.x, a.y);
    h[1] = __floats2half2_rn(a.z, a.w);
    h[2] = __floats2half2_rn(b.x, b.y);
    h[3] = __floats2half2_rn(b.z, b.w);
    hi[i] = *(const uint4*)h;
}

// ---------------- router: gates = softmax(x @ Wg), stored transposed --------
__global__ void router_kernel(const float* __restrict__ x,
                              const float* __restrict__ Wg) {
    int warp = (blockIdx.x * blockDim.x + threadIdx.x) >> 5;
    int lane = threadIdx.x & 31;
    if (warp >= NT) return;
    const float* xr = x + (size_t)warp * ND;
    float acc[NE];
#pragma unroll
    for (int e = 0; e < NE; e++) acc[e] = 0.0f;
    for (int d = lane; d < ND; d += 32) {
        float xv = xr[d];
        const float4 w0 = *(const float4*)(Wg + d * NE);
        const float4 w1 = *(const float4*)(Wg + d * NE + 4);
        acc[0] += xv * w0.x; acc[1] += xv * w0.y;
        acc[2] += xv * w0.z; acc[3] += xv * w0.w;
        acc[4] += xv * w1.x; acc[5] += xv * w1.y;
        acc[6] += xv * w1.z; acc[7] += xv * w1.w;
    }
#pragma unroll
    for (int off = 16; off > 0; off >>= 1) {
#pragma unroll
        for (int e = 0; e < NE; e++)
            acc[e] += __shfl_down_sync(0xffffffffu, acc[e], off);
    }
    if (lane == 0) {
        float m = acc[0];
#pragma unroll
        for (int e = 1; e < NE; e++) m = fmaxf(m, acc[e]);
        float s = 0.0f;
#pragma unroll
        for (int e = 0; e < NE; e++) { acc[e] = expf(acc[e] - m); s += acc[e]; }
        float inv = 1.0f / s;
#pragma unroll
        for (int e = 0; e < NE; e++) g_scoresT[e * NT + warp] = acc[e] * inv;
    }
}

// ---------------- exact top-C per expert via 4-pass radix select ------------
__global__ void topk_kernel() {
    int e = blockIdx.x;
    int tid = threadIdx.x;
    const float* s = g_scoresT + e * NT;

    __shared__ unsigned hist[256];
    __shared__ unsigned sh_prefix;
    __shared__ int sh_rem;

    unsigned prefix = 0;
    int remaining = NC;

    for (int shift = 24; shift >= 0; shift -= 8) {
        if (tid < 256) hist[tid] = 0;
        __syncthreads();
        unsigned mask = (shift == 24) ? 0u : (0xFFFFFFFFu << (shift + 8));
        for (int t = tid; t < NT; t += blockDim.x) {
            unsigned k = __float_as_uint(s[t]);
            if ((k & mask) == prefix) atomicAdd(&hist[(k >> shift) & 0xFFu], 1u);
        }
        __syncthreads();
        if (tid == 0) {
            int rem = remaining;
            int b = 0;
            for (int d = 255; d >= 0; d--) {
                int h = (int)hist[d];
                if (h >= rem) { b = d; break; }
                rem -= h;
            }
            sh_prefix = prefix | ((unsigned)b << shift);
            sh_rem = rem;
        }
        __syncthreads();
        prefix = sh_prefix;
        remaining = sh_rem;
        __syncthreads();
    }

    __shared__ int cnt_gt, cnt_eq;
    if (tid == 0) { cnt_gt = 0; cnt_eq = 0; }
    __syncthreads();
    int base = NC - remaining;
    for (int t = tid; t < NT; t += blockDim.x) {
        unsigned k = __float_as_uint(s[t]);
        if (k > prefix) {
            int p = atomicAdd(&cnt_gt, 1);
            g_idx[e * NC + p]  = t;
            g_vals[e * NC + p] = s[t];
        } else if (k == prefix) {
            int p = atomicAdd(&cnt_eq, 1);
            if (p < remaining) {
                g_idx[e * NC + base + p]  = t;
                g_vals[e * NC + base + p] = s[t];
            }
        }
    }
}

// ---------------- gelu (tanh approx via fast exp; matches jax to ~1e-6) -----
__device__ __forceinline__ float gelu_f(float v) {
    float u = 0.7978845608028654f * (v + 0.044715f * v * v * v);
    float t = 1.0f - 2.0f / (__expf(2.0f * u) + 1.0f);
    return 0.5f * v * (1.0f + t);
}

// ============================ split-fp16 mma.sync GEMM ========================
// CTA tile 128(M) x 128(N) x 32(K). 256 threads, 8 warps 2(m) x 4(n),
// warp tile 64x32. (a_hi + a_lo exact fp16 split) * b_hi -> 2 fp16 MMAs,
// fp32 accum. 3-stage cp.async pipeline, single top barrier, 2 CTAs/SM.

static constexpr int A_STRIDE = 40;                 // 16-bit units (80 B)
static constexpr int A_PLANE  = 128 * A_STRIDE;     // 5120
static constexpr int A_STAGE  = 2 * A_PLANE;        // hi + lo = 10240
static constexpr int B_BASE   = 3 * A_STAGE;        // 30720
static constexpr int B_STRIDE = 136;                // 16-bit units (272 B, 17*16)
static constexpr int B_PLANE  = 32 * B_STRIDE;      // 4352
static constexpr int SMEM_U16 = B_BASE + 3 * B_PLANE;        // 43776
static constexpr int GEMM_SMEM_BYTES = SMEM_U16 * 2;         // 87552

__device__ __forceinline__ uint32_t smem_u32(const void* p) {
    uint32_t a;
    asm("{ .reg .u64 t; cvta.to.shared.u64 t, %1; cvt.u32.u64 %0, t; }"
        : "=r"(a) : "l"(p));
    return a;
}

__device__ __forceinline__ void cp16(uint32_t dst, const void* src) {
    asm volatile("cp.async.cg.shared.global [%0], [%1], 16;"
                 :: "r"(dst), "l"(src) : "memory");
}
#define CP_COMMIT() asm volatile("cp.async.commit_group;" ::: "memory")
#define CP_WAIT1()  asm volatile("cp.async.wait_group 1;" ::: "memory")

__device__ __forceinline__ void ldsm4(uint32_t* r, uint32_t addr) {
    asm volatile("ldmatrix.sync.aligned.m8n8.x4.shared.b16 {%0,%1,%2,%3}, [%4];"
                 : "=r"(r[0]), "=r"(r[1]), "=r"(r[2]), "=r"(r[3]) : "r"(addr));
}
__device__ __forceinline__ void ldsm4t(uint32_t* r, uint32_t addr) {
    asm volatile("ldmatrix.sync.aligned.m8n8.x4.trans.shared.b16 {%0,%1,%2,%3}, [%4];"
                 : "=r"(r[0]), "=r"(r[1]), "=r"(r[2]), "=r"(r[3]) : "r"(addr));
}

__device__ __forceinline__ void mma_f16(float* d, const uint32_t* a,
                                        const uint32_t* b) {
    asm volatile(
        "mma.sync.aligned.m16n8k16.row.col.f32.f16.f16.f32 "
        "{%0,%1,%2,%3}, {%4,%5,%6,%7}, {%8,%9}, {%0,%1,%2,%3};"
        : "+f"(d[0]), "+f"(d[1]), "+f"(d[2]), "+f"(d[3])
        : "r"(a[0]), "r"(a[1]), "r"(a[2]), "r"(a[3]), "r"(b[0]), "r"(b[1]));
}

__device__ __forceinline__ void red_v2(float* ptr, float v0, float v1) {
    asm volatile("red.global.add.v2.f32 [%0], {%1, %2};"
                 :: "l"(ptr), "f"(v0), "f"(v1) : "memory");
}

// NCH chunks of K=32 per CTA per K-slice. GATHER: A rows via g_idx (lda=ND).
// GELU_EPI: write fp16-split gelu(acc+bias); else scatter-add into fp32 outa.
// blockIdx.z = K-slice; slice 0 adds bias. Ktot = full K (B expert stride).
template<int NCH, bool GATHER, bool GELU_EPI>
__global__ __launch_bounds__(256, 2) void gemm_tc_kernel(
    const uint16_t* __restrict__ Ah,
    const uint16_t* __restrict__ Al,
    const uint16_t* __restrict__ Bh,
    const float* __restrict__ bias,
    float* __restrict__ outa,
    __half* __restrict__ outbh,
    __half* __restrict__ outbl,
    int Nld, int lda, int Ktot) {
    extern __shared__ __align__(16) uint16_t sm[];
    __shared__ int   tok_s[128];
    __shared__ float val_s[128];

    const int tid = threadIdx.x;
    const int warp = tid >> 5;
    const int lane = tid & 31;
    const int wm = warp >> 2;          // 0..1  (64-row slab)
    const int wn = warp & 3;           // 0..3  (32-col slab)
    const int r = lane >> 2;           // 0..7 (accumulator row)
    const int c = lane & 3;            // 0..3 (accumulator col pair)
    const int quad = lane >> 3;        // 0..3 (ldmatrix matrix id)
    const int r8 = lane & 7;           // row within 8x8 matrix

    const int n0 = blockIdx.x * 128;
    const int m0 = blockIdx.y * 128;
    const int e = m0 >> 11;            // m0 / NC
    const int kbase = blockIdx.z * NCH * 32;
    const bool bias_en = (blockIdx.z == 0);

    if (tid < 128) {
        tok_s[tid] = g_idx[m0 + tid];
        val_s[tid] = g_vals[m0 + tid];
    }
    __syncthreads();

    const uint32_t sbase = smem_u32(sm);

    // ---- precomputed load pointers (advance one K-chunk per load_stage) ----
    const uint16_t* asrc[4];           // 2 planes x 2 iterations (A: 512 cp16)
    uint32_t adst0[4];
    const uint16_t* bsrc[2];           // 1 plane x 2 iterations (B: 512 cp16)
    uint32_t bdst0[2];
    {
        const uint16_t* aps[2] = {Ah, Al};
        const uint16_t* bp = Bh + (size_t)e * Ktot * Nld + n0;
#pragma unroll
        for (int p = 0; p < 2; p++) {
#pragma unroll
            for (int i = 0; i < 2; i++) {          // A: 128 rows x 4 segs
                int lin = tid + 256 * i;
                int row = lin >> 2;
                int seg = (lin & 3) * 8;
                int j = p * 2 + i;
                asrc[j] = GATHER
                    ? (aps[p] + (size_t)tok_s[row] * lda + kbase + seg)
                    : (aps[p] + (size_t)(m0 + row) * lda + kbase + seg);
                adst0[j] = sbase + (uint32_t)(p * A_PLANE + row * A_STRIDE + seg) * 2;
            }
        }
#pragma unroll
        for (int i = 0; i < 2; i++) {              // B: 32 rows x 16 segs
            int lin = tid + 256 * i;
            int row = lin >> 4;                    // 0..31
            int seg = (lin & 15) * 8;
            bsrc[i] = bp + (size_t)(kbase + row) * Nld + seg;
            bdst0[i] = sbase + (uint32_t)(B_BASE + row * B_STRIDE + seg) * 2;
        }
    }

    auto load_stage = [&](int s) {
        const uint32_t ao = (uint32_t)s * (A_STAGE * 2);
        const uint32_t bo = (uint32_t)s * (B_PLANE * 2);
#pragma unroll
        for (int j = 0; j < 4; j++) {
            cp16(adst0[j] + ao, asrc[j]);
            asrc[j] += 32;
        }
#pragma unroll
        for (int j = 0; j < 2; j++) {
            cp16(bdst0[j] + bo, bsrc[j]);
            bsrc[j] += (size_t)32 * Nld;
        }
    };

    float acc[4][4][4];                // [mt][nt][frag]
#pragma unroll
    for (int mt = 0; mt < 4; mt++)
#pragma unroll
        for (int nt = 0; nt < 4; nt++)
#pragma unroll
            for (int i = 0; i < 4; i++) acc[mt][nt][i] = 0.0f;

    // prologue: fill stages 0, 1 (prefetch distance 2)
    load_stage(0);
    CP_COMMIT();
    load_stage(1);
    CP_COMMIT();

    int s = 0;                         // current stage, wraps mod 3
    int sload = 2;                     // stage to load next, wraps mod 3
#pragma unroll 1
    for (int ch = 0; ch < NCH; ch++) {
        CP_WAIT1();
        __syncthreads();               // single barrier: also guards stage reuse
        if (ch + 2 < NCH) load_stage(sload);
        CP_COMMIT();   // unconditional: keeps wait_group bookkeeping exact

        const uint32_t sa = sbase + (uint32_t)s * (A_STAGE * 2);
        const uint32_t sb = sbase + (uint32_t)(B_BASE * 2 + s * (B_PLANE * 2));
#pragma unroll
        for (int ks = 0; ks < 2; ks++) {
            // ---- A fragments: hi/lo x 4 m-tiles via ldmatrix.x4 ----
            uint32_t ah[4][4], al[4][4];
            {
                const int m_local = wm * 64 + (quad & 1) * 8 + r8;
                const int k_off = ks * 16 + (quad >> 1) * 8;
                const uint32_t abase = sa +
                    (uint32_t)(m_local * A_STRIDE + k_off) * 2;
#pragma unroll
                for (int mt = 0; mt < 4; mt++) {
                    ldsm4(ah[mt], abase + (uint32_t)(mt * 16 * A_STRIDE) * 2);
                    ldsm4(al[mt], abase + (uint32_t)(A_PLANE + mt * 16 * A_STRIDE) * 2);
                }
            }
            // ---- B fragments per 16-col group; term-major MMA ordering ----
            {
                const int k_row = ks * 16 + (quad & 1) * 8 + r8;
                const int n_col = wn * 32 + (quad >> 1) * 8;
                const uint32_t bbase = sb +
                    (uint32_t)(k_row * B_STRIDE + n_col) * 2;
#pragma unroll
                for (int nt2 = 0; nt2 < 2; nt2++) {
                    uint32_t bh[4];
                    ldsm4t(bh, bbase + (uint32_t)(nt2 * 16) * 2);
                    const int nt = nt2 * 2;
                    // a_hi*b_hi
#pragma unroll
                    for (int mt = 0; mt < 4; mt++) {
                        mma_f16(acc[mt][nt],     ah[mt], bh);
                        mma_f16(acc[mt][nt + 1], ah[mt], bh + 2);
                    }
                    // a_lo*b_hi
#pragma unroll
                    for (int mt = 0; mt < 4; mt++) {
                        mma_f16(acc[mt][nt],     al[mt], bh);
                        mma_f16(acc[mt][nt + 1], al[mt], bh + 2);
                    }
                }
            }
        }
        s = (s == 2) ? 0 : s + 1;
        sload = (sload == 2) ? 0 : sload + 1;
    }

    // ---------------- epilogue -----------------------------------------------
#pragma unroll
    for (int mt = 0; mt < 4; mt++) {
        const int lm0 = wm * 64 + mt * 16 + r;       // local row of acc[0],acc[1]
        const int lm1 = lm0 + 8;                     // local row of acc[2],acc[3]
#pragma unroll
        for (int nt = 0; nt < 4; nt++) {
            const int bcol = n0 + wn * 32 + nt * 8 + c * 2;
            const float bb0 = bias_en ? bias[e * Nld + bcol] : 0.0f;
            const float bb1 = bias_en ? bias[e * Nld + bcol + 1] : 0.0f;
            if (GELU_EPI) {
                float v00 = gelu_f(acc[mt][nt][0] + bb0);
                float v01 = gelu_f(acc[mt][nt][1] + bb1);
                float v10 = gelu_f(acc[mt][nt][2] + bb0);
                float v11 = gelu_f(acc[mt][nt][3] + bb1);
                __half h00 = __float2half_rn(v00);
                __half h01 = __float2half_rn(v01);
                __half h10 = __float2half_rn(v10);
                __half h11 = __float2half_rn(v11);
                __half2 hp0 = __halves2half2(h00, h01);
                __half2 hp1 = __halves2half2(h10, h11);
                __half2 lp0 = __floats2half2_rn(v00 - __half2float(h00),
                                                v01 - __half2float(h01));
                __half2 lp1 = __floats2half2_rn(v10 - __half2float(h10),
                                                v11 - __half2float(h11));
                *(__half2*)(outbh + (size_t)(m0 + lm0) * Nld + bcol) = hp0;
                *(__half2*)(outbh + (size_t)(m0 + lm1) * Nld + bcol) = hp1;
                *(__half2*)(outbl + (size_t)(m0 + lm0) * Nld + bcol) = lp0;
                *(__half2*)(outbl + (size_t)(m0 + lm1) * Nld + bcol) = lp1;
            } else {
                const float w0 = val_s[lm0];
                const float w1 = val_s[lm1];
                float* p0 = outa + (size_t)tok_s[lm0] * ND + bcol;
                float* p1 = outa + (size_t)tok_s[lm1] * ND + bcol;
                red_v2(p0, (acc[mt][nt][0] + bb0) * w0, (acc[mt][nt][1] + bb1) * w0);
                red_v2(p1, (acc[mt][nt][2] + bb0) * w1, (acc[mt][nt][3] + bb1) * w1);
            }
        }
    }
}

// ============================ host launch =====================================
extern "C" void kernel_launch(void* const* d_in, const int* in_sizes, int n_in,
                              void* d_out, int out_size) {
    const float* x  = (const float*)d_in[0];   // [T, D]
    const float* Wg = (const float*)d_in[1];   // [D, E]
    const float* W1 = (const float*)d_in[2];   // [E, D, F]
    const float* b1 = (const float*)d_in[3];   // [E, F]
    const float* W2 = (const float*)d_in[4];   // [E, F, D]
    const float* b2 = (const float*)d_in[5];   // [E, D]
    float* out = (float*)d_out;

    void *p_xh, *p_xl, *p_w1h, *p_w2h, *p_hh, *p_hl;
    cudaGetSymbolAddress(&p_xh, g_xh);
    cudaGetSymbolAddress(&p_xl, g_xl);
    cudaGetSymbolAddress(&p_w1h, g_w1h);
    cudaGetSymbolAddress(&p_w2h, g_w2h);
    cudaGetSymbolAddress(&p_hh, g_hh);
    cudaGetSymbolAddress(&p_hl, g_hl);

    cudaFuncSetAttribute(
        (const void*)gemm_tc_kernel<32, true, true>,
        cudaFuncAttributeMaxDynamicSharedMemorySize, GEMM_SMEM_BYTES);
    cudaFuncSetAttribute(
        (const void*)gemm_tc_kernel<64, false, false>,
        cudaFuncAttributeMaxDynamicSharedMemorySize, GEMM_SMEM_BYTES);

    size_t n_main = (size_t)NT * ND;
    init_out_kernel<<<512, 256>>>(out, n_main, (size_t)out_size);
    router_kernel<<<NT / 32, 1024>>>(x, Wg);
    topk_kernel<<<NE, 1024>>>();

    // Pre-split: x -> fp16 hi/lo; W1, W2 -> fp16 hi only.
    split_f16_kernel<<<(NT * ND / 8 + 255) / 256, 256>>>(
        (const float4*)x, (uint4*)p_xh, (uint4*)p_xl, (size_t)NT * ND / 8);
    cvt_f16_kernel<<<((size_t)NE * ND * NF / 8 + 255) / 256, 256>>>(
        (const float4*)W1, (uint4*)p_w1h, (size_t)NE * ND * NF / 8);
    cvt_f16_kernel<<<((size_t)NE * NF * ND / 8 + 255) / 256, 256>>>(
        (const float4*)W2, (uint4*)p_w2h, (size_t)NE * NF * ND / 8);

    // GEMM1: h = gelu(x[idx] @ W1_hi[e] + b1[e])   fp16 2-term
    gemm_tc_kernel<32, true, true>
        <<<dim3(NF / 128, NM / 128, 1), 256, GEMM_SMEM_BYTES>>>(
            (const uint16_t*)p_xh, (const uint16_t*)p_xl,
            (const uint16_t*)p_w1h,
            b1, nullptr,
            (__half*)p_hh, (__half*)p_hl, NF, ND, ND);

    // GEMM2: out[tok] += val*(h @ W2_hi[e] + b2[e])   fp16 2-term, split-K = 2
    gemm_tc_kernel<64, false, false>
        <<<dim3(ND / 128, NM / 128, 2), 256, GEMM_SMEM_BYTES>>>(
            (const uint16_t*)p_hh, (const uint16_t*)p_hl,
            (const uint16_t*)p_w2h,
            b2, out, nullptr, nullptr, ND, NF, NF);
}

// round 15
// speedup vs baseline: 2.4303x; 1.7536x over previous
#include <cuda_runtime.h>
#include <cuda_fp16.h>
#include <cstdint>

// Problem constants
#define NE 8
#define ND 1024
#define NF 4096
#define NT 8192
#define NC 2048
#define NM (NE * NC)   // 16384 rows through the expert FFN

// ---------------- scratch (device globals; no runtime allocation) ----------
__device__ float g_scoresT[NE * NT];              // gates^T  [E, T]
__device__ int   g_idx[NM];                       // selected token ids [E*C]
__device__ float g_vals[NM];                      // routing probs of selected
__device__ __half g_xh[(size_t)NT * ND];          // x fp16
__device__ __half g_w1h[(size_t)NE * ND * NF];    // W1 fp16
__device__ __half g_w2h[(size_t)NE * NF * ND];    // W2 fp16
__device__ __half g_hh[(size_t)NM * NF];          // gelu output fp16

// ---------------- init output ------------------------------------------------
__global__ void init_out_kernel(float* out, size_t n_main, size_t total) {
    size_t i = (size_t)blockIdx.x * blockDim.x + threadIdx.x;
    size_t stride = (size_t)gridDim.x * blockDim.x;
    for (; i < total; i += stride) {
        if (i < n_main)       out[i] = 0.0f;
        else if (i == n_main) out[i] = 2.0f;   // aux_loss = E*(C/T)*1 = 2 analytically
        else                  out[i] = 0.0f;
    }
}

// ---------------- fp32 -> fp16 convert, 8 floats/thread ---------------------
__global__ void cvt_f16_kernel(const float4* __restrict__ in,
                               uint4* __restrict__ hi, size_t n8) {
    size_t i = (size_t)blockIdx.x * blockDim.x + threadIdx.x;
    if (i >= n8) return;
    float4 a = in[2 * i];
    float4 b = in[2 * i + 1];
    __half2 h[4];
    h[0] = __floats2half2_rn(a.x, a.y);
    h[1] = __floats2half2_rn(a.z, a.w);
    h[2] = __floats2half2_rn(b.x, b.y);
    h[3] = __floats2half2_rn(b.z, b.w);
    hi[i] = *(const uint4*)h;
}

// ---------------- router: gates = softmax(x @ Wg), stored transposed --------
__global__ void router_kernel(const float* __restrict__ x,
                              const float* __restrict__ Wg) {
    int warp = (blockIdx.x * blockDim.x + threadIdx.x) >> 5;
    int lane = threadIdx.x & 31;
    if (warp >= NT) return;
    const float* xr = x + (size_t)warp * ND;
    float acc[NE];
#pragma unroll
    for (int e = 0; e < NE; e++) acc[e] = 0.0f;
    for (int d = lane; d < ND; d += 32) {
        float xv = xr[d];
        const float4 w0 = *(const float4*)(Wg + d * NE);
        const float4 w1 = *(const float4*)(Wg + d * NE + 4);
        acc[0] += xv * w0.x; acc[1] += xv * w0.y;
        acc[2] += xv * w0.z; acc[3] += xv * w0.w;
        acc[4] += xv * w1.x; acc[5] += xv * w1.y;
        acc[6] += xv * w1.z; acc[7] += xv * w1.w;
    }
#pragma unroll
    for (int off = 16; off > 0; off >>= 1) {
#pragma unroll
        for (int e = 0; e < NE; e++)
            acc[e] += __shfl_down_sync(0xffffffffu, acc[e], off);
    }
    if (lane == 0) {
        float m = acc[0];
#pragma unroll
        for (int e = 1; e < NE; e++) m = fmaxf(m, acc[e]);
        float s = 0.0f;
#pragma unroll
        for (int e = 0; e < NE; e++) { acc[e] = expf(acc[e] - m); s += acc[e]; }
        float inv = 1.0f / s;
#pragma unroll
        for (int e = 0; e < NE; e++) g_scoresT[e * NT + warp] = acc[e] * inv;
    }
}

// ---------------- exact top-C per expert via 4-pass radix select ------------
__global__ void topk_kernel() {
    int e = blockIdx.x;
    int tid = threadIdx.x;
    const float* s = g_scoresT + e * NT;

    __shared__ unsigned hist[256];
    __shared__ unsigned sh_prefix;
    __shared__ int sh_rem;

    unsigned prefix = 0;
    int remaining = NC;

    for (int shift = 24; shift >= 0; shift -= 8) {
        if (tid < 256) hist[tid] = 0;
        __syncthreads();
        unsigned mask = (shift == 24) ? 0u : (0xFFFFFFFFu << (shift + 8));
        for (int t = tid; t < NT; t += blockDim.x) {
            unsigned k = __float_as_uint(s[t]);
            if ((k & mask) == prefix) atomicAdd(&hist[(k >> shift) & 0xFFu], 1u);
        }
        __syncthreads();
        if (tid == 0) {
            int rem = remaining;
            int b = 0;
            for (int d = 255; d >= 0; d--) {
                int h = (int)hist[d];
                if (h >= rem) { b = d; break; }
                rem -= h;
            }
            sh_prefix = prefix | ((unsigned)b << shift);
            sh_rem = rem;
        }
        __syncthreads();
        prefix = sh_prefix;
        remaining = sh_rem;
        __syncthreads();
    }

    __shared__ int cnt_gt, cnt_eq;
    if (tid == 0) { cnt_gt = 0; cnt_eq = 0; }
    __syncthreads();
    int base = NC - remaining;
    for (int t = tid; t < NT; t += blockDim.x) {
        unsigned k = __float_as_uint(s[t]);
        if (k > prefix) {
            int p = atomicAdd(&cnt_gt, 1);
            g_idx[e * NC + p]  = t;
            g_vals[e * NC + p] = s[t];
        } else if (k == prefix) {
            int p = atomicAdd(&cnt_eq, 1);
            if (p < remaining) {
                g_idx[e * NC + base + p]  = t;
                g_vals[e * NC + base + p] = s[t];
            }
        }
    }
}

// ---------------- gelu (tanh approx via fast exp; matches jax to ~1e-6) -----
__device__ __forceinline__ float gelu_f(float v) {
    float u = 0.7978845608028654f * (v + 0.044715f * v * v * v);
    float t = 1.0f - 2.0f / (__expf(2.0f * u) + 1.0f);
    return 0.5f * v * (1.0f + t);
}

// ============================ fp16 mma.sync GEMM ==============================
// CTA tile 128(M) x 128(N) x 32(K). 256 threads, 8 warps 2(m) x 4(n),
// warp tile 64x32. Plain fp16 MMA (1 term), fp32 accum.
// 3-stage cp.async pipeline, single top barrier, 2 CTAs/SM.

static constexpr int A_STRIDE = 40;                 // 16-bit units (80 B)
static constexpr int A_PLANE  = 128 * A_STRIDE;     // 5120
static constexpr int B_BASE   = 3 * A_PLANE;        // 15360
static constexpr int B_STRIDE = 136;                // 16-bit units (272 B, 17*16)
static constexpr int B_PLANE  = 32 * B_STRIDE;      // 4352
static constexpr int SMEM_U16 = B_BASE + 3 * B_PLANE;        // 28416
static constexpr int GEMM_SMEM_BYTES = SMEM_U16 * 2;         // 56832

__device__ __forceinline__ uint32_t smem_u32(const void* p) {
    uint32_t a;
    asm("{ .reg .u64 t; cvta.to.shared.u64 t, %1; cvt.u32.u64 %0, t; }"
        : "=r"(a) : "l"(p));
    return a;
}

__device__ __forceinline__ void cp16(uint32_t dst, const void* src) {
    asm volatile("cp.async.cg.shared.global [%0], [%1], 16;"
                 :: "r"(dst), "l"(src) : "memory");
}
#define CP_COMMIT() asm volatile("cp.async.commit_group;" ::: "memory")
#define CP_WAIT1()  asm volatile("cp.async.wait_group 1;" ::: "memory")

__device__ __forceinline__ void ldsm4(uint32_t* r, uint32_t addr) {
    asm volatile("ldmatrix.sync.aligned.m8n8.x4.shared.b16 {%0,%1,%2,%3}, [%4];"
                 : "=r"(r[0]), "=r"(r[1]), "=r"(r[2]), "=r"(r[3]) : "r"(addr));
}
__device__ __forceinline__ void ldsm4t(uint32_t* r, uint32_t addr) {
    asm volatile("ldmatrix.sync.aligned.m8n8.x4.trans.shared.b16 {%0,%1,%2,%3}, [%4];"
                 : "=r"(r[0]), "=r"(r[1]), "=r"(r[2]), "=r"(r[3]) : "r"(addr));
}

__device__ __forceinline__ void mma_f16(float* d, const uint32_t* a,
                                        const uint32_t* b) {
    asm volatile(
        "mma.sync.aligned.m16n8k16.row.col.f32.f16.f16.f32 "
        "{%0,%1,%2,%3}, {%4,%5,%6,%7}, {%8,%9}, {%0,%1,%2,%3};"
        : "+f"(d[0]), "+f"(d[1]), "+f"(d[2]), "+f"(d[3])
        : "r"(a[0]), "r"(a[1]), "r"(a[2]), "r"(a[3]), "r"(b[0]), "r"(b[1]));
}

__device__ __forceinline__ void red_v2(float* ptr, float v0, float v1) {
    asm volatile("red.global.add.v2.f32 [%0], {%1, %2};"
                 :: "l"(ptr), "f"(v0), "f"(v1) : "memory");
}

// NCH chunks of K=32 per CTA per K-slice. GATHER: A rows via g_idx (lda=ND).
// GELU_EPI: write fp16 gelu(acc+bias); else scatter-add into fp32 outa.
// blockIdx.z = K-slice; slice 0 adds bias. Ktot = full K (B expert stride).
template<int NCH, bool GATHER, bool GELU_EPI>
__global__ __launch_bounds__(256, 2) void gemm_tc_kernel(
    const uint16_t* __restrict__ Ah,
    const uint16_t* __restrict__ Bh,
    const float* __restrict__ bias,
    float* __restrict__ outa,
    __half* __restrict__ outbh,
    int Nld, int lda, int Ktot) {
    extern __shared__ __align__(16) uint16_t sm[];
    __shared__ int   tok_s[128];
    __shared__ float val_s[128];

    const int tid = threadIdx.x;
    const int warp = tid >> 5;
    const int lane = tid & 31;
    const int wm = warp >> 2;          // 0..1  (64-row slab)
    const int wn = warp & 3;           // 0..3  (32-col slab)
    const int r = lane >> 2;           // 0..7 (accumulator row)
    const int c = lane & 3;            // 0..3 (accumulator col pair)
    const int quad = lane >> 3;        // 0..3 (ldmatrix matrix id)
    const int r8 = lane & 7;           // row within 8x8 matrix

    const int n0 = blockIdx.x * 128;
    const int m0 = blockIdx.y * 128;
    const int e = m0 >> 11;            // m0 / NC
    const int kbase = blockIdx.z * NCH * 32;
    const bool bias_en = (blockIdx.z == 0);

    if (tid < 128) {
        tok_s[tid] = g_idx[m0 + tid];
        val_s[tid] = g_vals[m0 + tid];
    }
    __syncthreads();

    const uint32_t sbase = smem_u32(sm);

    // ---- precomputed load pointers (advance one K-chunk per load_stage) ----
    const uint16_t* asrc[2];           // 2 iterations (A: 512 cp16)
    uint32_t adst0[2];
    const uint16_t* bsrc[2];           // 2 iterations (B: 512 cp16)
    uint32_t bdst0[2];
    {
        const uint16_t* bp = Bh + (size_t)e * Ktot * Nld + n0;
#pragma unroll
        for (int i = 0; i < 2; i++) {              // A: 128 rows x 4 segs
            int lin = tid + 256 * i;
            int row = lin >> 2;
            int seg = (lin & 3) * 8;
            asrc[i] = GATHER
                ? (Ah + (size_t)tok_s[row] * lda + kbase + seg)
                : (Ah + (size_t)(m0 + row) * lda + kbase + seg);
            adst0[i] = sbase + (uint32_t)(row * A_STRIDE + seg) * 2;
        }
#pragma unroll
        for (int i = 0; i < 2; i++) {              // B: 32 rows x 16 segs
            int lin = tid + 256 * i;
            int row = lin >> 4;                    // 0..31
            int seg = (lin & 15) * 8;
            bsrc[i] = bp + (size_t)(kbase + row) * Nld + seg;
            bdst0[i] = sbase + (uint32_t)(B_BASE + row * B_STRIDE + seg) * 2;
        }
    }

    auto load_stage = [&](int s) {
        const uint32_t ao = (uint32_t)s * (A_PLANE * 2);
        const uint32_t bo = (uint32_t)s * (B_PLANE * 2);
#pragma unroll
        for (int j = 0; j < 2; j++) {
            cp16(adst0[j] + ao, asrc[j]);
            asrc[j] += 32;
        }
#pragma unroll
        for (int j = 0; j < 2; j++) {
            cp16(bdst0[j] + bo, bsrc[j]);
            bsrc[j] += (size_t)32 * Nld;
        }
    };

    float acc[4][4][4];                // [mt][nt][frag]
#pragma unroll
    for (int mt = 0; mt < 4; mt++)
#pragma unroll
        for (int nt = 0; nt < 4; nt++)
#pragma unroll
            for (int i = 0; i < 4; i++) acc[mt][nt][i] = 0.0f;

    // prologue: fill stages 0, 1 (prefetch distance 2)
    load_stage(0);
    CP_COMMIT();
    load_stage(1);
    CP_COMMIT();

    int s = 0;                         // current stage, wraps mod 3
    int sload = 2;                     // stage to load next, wraps mod 3
#pragma unroll 1
    for (int ch = 0; ch < NCH; ch++) {
        CP_WAIT1();
        __syncthreads();               // single barrier: also guards stage reuse
        if (ch + 2 < NCH) load_stage(sload);
        CP_COMMIT();   // unconditional: keeps wait_group bookkeeping exact

        const uint32_t sa = sbase + (uint32_t)s * (A_PLANE * 2);
        const uint32_t sb = sbase + (uint32_t)(B_BASE * 2 + s * (B_PLANE * 2));
#pragma unroll
        for (int ks = 0; ks < 2; ks++) {
            // ---- A fragments: 4 m-tiles via ldmatrix.x4 ----
            uint32_t ah[4][4];
            {
                const int m_local = wm * 64 + (quad & 1) * 8 + r8;
                const int k_off = ks * 16 + (quad >> 1) * 8;
                const uint32_t abase = sa +
                    (uint32_t)(m_local * A_STRIDE + k_off) * 2;
#pragma unroll
                for (int mt = 0; mt < 4; mt++)
                    ldsm4(ah[mt], abase + (uint32_t)(mt * 16 * A_STRIDE) * 2);
            }
            // ---- B fragments per 16-col group ----
            {
                const int k_row = ks * 16 + (quad & 1) * 8 + r8;
                const int n_col = wn * 32 + (quad >> 1) * 8;
                const uint32_t bbase = sb +
                    (uint32_t)(k_row * B_STRIDE + n_col) * 2;
#pragma unroll
                for (int nt2 = 0; nt2 < 2; nt2++) {
                    uint32_t bh[4];
                    ldsm4t(bh, bbase + (uint32_t)(nt2 * 16) * 2);
                    const int nt = nt2 * 2;
#pragma unroll
                    for (int mt = 0; mt < 4; mt++) {
                        mma_f16(acc[mt][nt],     ah[mt], bh);
                        mma_f16(acc[mt][nt + 1], ah[mt], bh + 2);
                    }
                }
            }
        }
        s = (s == 2) ? 0 : s + 1;
        sload = (sload == 2) ? 0 : sload + 1;
    }

    // ---------------- epilogue -----------------------------------------------
#pragma unroll
    for (int mt = 0; mt < 4; mt++) {
        const int lm0 = wm * 64 + mt * 16 + r;       // local row of acc[0],acc[1]
        const int lm1 = lm0 + 8;                     // local row of acc[2],acc[3]
#pragma unroll
        for (int nt = 0; nt < 4; nt++) {
            const int bcol = n0 + wn * 32 + nt * 8 + c * 2;
            const float bb0 = bias_en ? bias[e * Nld + bcol] : 0.0f;
            const float bb1 = bias_en ? bias[e * Nld + bcol + 1] : 0.0f;
            if (GELU_EPI) {
                __half2 hp0 = __floats2half2_rn(gelu_f(acc[mt][nt][0] + bb0),
                                                gelu_f(acc[mt][nt][1] + bb1));
                __half2 hp1 = __floats2half2_rn(gelu_f(acc[mt][nt][2] + bb0),
                                                gelu_f(acc[mt][nt][3] + bb1));
                *(__half2*)(outbh + (size_t)(m0 + lm0) * Nld + bcol) = hp0;
                *(__half2*)(outbh + (size_t)(m0 + lm1) * Nld + bcol) = hp1;
            } else {
                const float w0 = val_s[lm0];
                const float w1 = val_s[lm1];
                float* p0 = outa + (size_t)tok_s[lm0] * ND + bcol;
                float* p1 = outa + (size_t)tok_s[lm1] * ND + bcol;
                red_v2(p0, (acc[mt][nt][0] + bb0) * w0, (acc[mt][nt][1] + bb1) * w0);
                red_v2(p1, (acc[mt][nt][2] + bb0) * w1, (acc[mt][nt][3] + bb1) * w1);
            }
        }
    }
}

// ============================ host launch =====================================
extern "C" void kernel_launch(void* const* d_in, const int* in_sizes, int n_in,
                              void* d_out, int out_size) {
    const float* x  = (const float*)d_in[0];   // [T, D]
    const float* Wg = (const float*)d_in[1];   // [D, E]
    const float* W1 = (const float*)d_in[2];   // [E, D, F]
    const float* b1 = (const float*)d_in[3];   // [E, F]
    const float* W2 = (const float*)d_in[4];   // [E, F, D]
    const float* b2 = (const float*)d_in[5];   // [E, D]
    float* out = (float*)d_out;

    void *p_xh, *p_w1h, *p_w2h, *p_hh;
    cudaGetSymbolAddress(&p_xh, g_xh);
    cudaGetSymbolAddress(&p_w1h, g_w1h);
    cudaGetSymbolAddress(&p_w2h, g_w2h);
    cudaGetSymbolAddress(&p_hh, g_hh);

    cudaFuncSetAttribute(
        (const void*)gemm_tc_kernel<32, true, true>,
        cudaFuncAttributeMaxDynamicSharedMemorySize, GEMM_SMEM_BYTES);
    cudaFuncSetAttribute(
        (const void*)gemm_tc_kernel<64, false, false>,
        cudaFuncAttributeMaxDynamicSharedMemorySize, GEMM_SMEM_BYTES);

    size_t n_main = (size_t)NT * ND;
    init_out_kernel<<<512, 256>>>(out, n_main, (size_t)out_size);
    router_kernel<<<NT / 32, 1024>>>(x, Wg);
    topk_kernel<<<NE, 1024>>>();

    // Convert operands to fp16.
    cvt_f16_kernel<<<(NT * ND / 8 + 255) / 256, 256>>>(
        (const float4*)x, (uint4*)p_xh, (size_t)NT * ND / 8);
    cvt_f16_kernel<<<((size_t)NE * ND * NF / 8 + 255) / 256, 256>>>(
        (const float4*)W1, (uint4*)p_w1h, (size_t)NE * ND * NF / 8);
    cvt_f16_kernel<<<((size_t)NE * NF * ND / 8 + 255) / 256, 256>>>(
        (const float4*)W2, (uint4*)p_w2h, (size_t)NE * NF * ND / 8);

    // GEMM1: h = gelu(x[idx] @ W1[e] + b1[e])   fp16 1-term
    gemm_tc_kernel<32, true, true>
        <<<dim3(NF / 128, NM / 128, 1), 256, GEMM_SMEM_BYTES>>>(
            (const uint16_t*)p_xh, (const uint16_t*)p_w1h,
            b1, nullptr, (__half*)p_hh, NF, ND, ND);

    // GEMM2: out[tok] += val*(h @ W2[e] + b2[e])   fp16 1-term, split-K = 2
    gemm_tc_kernel<64, false, false>
        <<<dim3(ND / 128, NM / 128, 2), 256, GEMM_SMEM_BYTES>>>(
            (const uint16_t*)p_hh, (const uint16_t*)p_w2h,
            b2, out, nullptr, ND, NF, NF);
}

// round 16
// speedup vs baseline: 2.5163x; 1.0354x over previous
#include <cuda_runtime.h>
#include <cuda_fp16.h>
#include <cstdint>

// Problem constants
#define NE 8
#define ND 1024
#define NF 4096
#define NT 8192
#define NC 2048
#define NM (NE * NC)   // 16384 rows through the expert FFN

// ---------------- scratch (device globals; no runtime allocation) ----------
__device__ float g_scoresT[NE * NT];              // gates^T  [E, T]
__device__ int   g_idx[NM];                       // selected token ids [E*C]
__device__ float g_vals[NM];                      // routing probs of selected
__device__ __half g_xh[(size_t)NT * ND];          // x fp16
__device__ __half g_w1h[(size_t)NE * ND * NF];    // W1 fp16
__device__ __half g_w2h[(size_t)NE * NF * ND];    // W2 fp16
__device__ __half g_hh[(size_t)NM * NF];          // gelu output fp16

// ---------------- init output ------------------------------------------------
__global__ void init_out_kernel(float* out, size_t n_main, size_t total) {
    size_t i = (size_t)blockIdx.x * blockDim.x + threadIdx.x;
    size_t stride = (size_t)gridDim.x * blockDim.x;
    for (; i < total; i += stride) {
        if (i < n_main)       out[i] = 0.0f;
        else if (i == n_main) out[i] = 2.0f;   // aux_loss = E*(C/T)*1 = 2 analytically
        else                  out[i] = 0.0f;
    }
}

// ---------------- fp32 -> fp16 convert, 8 floats/thread ---------------------
__global__ void cvt_f16_kernel(const float4* __restrict__ in,
                               uint4* __restrict__ hi, size_t n8) {
    size_t i = (size_t)blockIdx.x * blockDim.x + threadIdx.x;
    if (i >= n8) return;
    float4 a = in[2 * i];
    float4 b = in[2 * i + 1];
    __half2 h[4];
    h[0] = __floats2half2_rn(a.x, a.y);
    h[1] = __floats2half2_rn(a.z, a.w);
    h[2] = __floats2half2_rn(b.x, b.y);
    h[3] = __floats2half2_rn(b.z, b.w);
    hi[i] = *(const uint4*)h;
}

// ---------------- router: gates = softmax(x @ Wg), stored transposed --------
__global__ void router_kernel(const float* __restrict__ x,
                              const float* __restrict__ Wg) {
    int warp = (blockIdx.x * blockDim.x + threadIdx.x) >> 5;
    int lane = threadIdx.x & 31;
    if (warp >= NT) return;
    const float* xr = x + (size_t)warp * ND;
    float acc[NE];
#pragma unroll
    for (int e = 0; e < NE; e++) acc[e] = 0.0f;
    for (int d = lane; d < ND; d += 32) {
        float xv = xr[d];
        const float4 w0 = *(const float4*)(Wg + d * NE);
        const float4 w1 = *(const float4*)(Wg + d * NE + 4);
        acc[0] += xv * w0.x; acc[1] += xv * w0.y;
        acc[2] += xv * w0.z; acc[3] += xv * w0.w;
        acc[4] += xv * w1.x; acc[5] += xv * w1.y;
        acc[6] += xv * w1.z; acc[7] += xv * w1.w;
    }
#pragma unroll
    for (int off = 16; off > 0; off >>= 1) {
#pragma unroll
        for (int e = 0; e < NE; e++)
            acc[e] += __shfl_down_sync(0xffffffffu, acc[e], off);
    }
    if (lane == 0) {
        float m = acc[0];
#pragma unroll
        for (int e = 1; e < NE; e++) m = fmaxf(m, acc[e]);
        float s = 0.0f;
#pragma unroll
        for (int e = 0; e < NE; e++) { acc[e] = expf(acc[e] - m); s += acc[e]; }
        float inv = 1.0f / s;
#pragma unroll
        for (int e = 0; e < NE; e++) g_scoresT[e * NT + warp] = acc[e] * inv;
    }
}

// ---------------- exact top-C per expert via 4-pass radix select ------------
__global__ void topk_kernel() {
    int e = blockIdx.x;
    int tid = threadIdx.x;
    const float* s = g_scoresT + e * NT;

    __shared__ unsigned hist[256];
    __shared__ unsigned sh_prefix;
    __shared__ int sh_rem;

    unsigned prefix = 0;
    int remaining = NC;

    for (int shift = 24; shift >= 0; shift -= 8) {
        if (tid < 256) hist[tid] = 0;
        __syncthreads();
        unsigned mask = (shift == 24) ? 0u : (0xFFFFFFFFu << (shift + 8));
        for (int t = tid; t < NT; t += blockDim.x) {
            unsigned k = __float_as_uint(s[t]);
            if ((k & mask) == prefix) atomicAdd(&hist[(k >> shift) & 0xFFu], 1u);
        }
        __syncthreads();
        if (tid == 0) {
            int rem = remaining;
            int b = 0;
            for (int d = 255; d >= 0; d--) {
                int h = (int)hist[d];
                if (h >= rem) { b = d; break; }
                rem -= h;
            }
            sh_prefix = prefix | ((unsigned)b << shift);
            sh_rem = rem;
        }
        __syncthreads();
        prefix = sh_prefix;
        remaining = sh_rem;
        __syncthreads();
    }

    __shared__ int cnt_gt, cnt_eq;
    if (tid == 0) { cnt_gt = 0; cnt_eq = 0; }
    __syncthreads();
    int base = NC - remaining;
    for (int t = tid; t < NT; t += blockDim.x) {
        unsigned k = __float_as_uint(s[t]);
        if (k > prefix) {
            int p = atomicAdd(&cnt_gt, 1);
            g_idx[e * NC + p]  = t;
            g_vals[e * NC + p] = s[t];
        } else if (k == prefix) {
            int p = atomicAdd(&cnt_eq, 1);
            if (p < remaining) {
                g_idx[e * NC + base + p]  = t;
                g_vals[e * NC + base + p] = s[t];
            }
        }
    }
}

// ---------------- gelu (tanh approx via fast exp; matches jax to ~1e-6) -----
__device__ __forceinline__ float gelu_f(float v) {
    float u = 0.7978845608028654f * (v + 0.044715f * v * v * v);
    float t = 1.0f - 2.0f / (__expf(2.0f * u) + 1.0f);
    return 0.5f * v * (1.0f + t);
}

// ============================ fp16 mma.sync GEMM ==============================
// CTA tile 128(M) x 128(N) x 64(K). 256 threads, 8 warps 2(m) x 4(n),
// warp tile 64x32. Plain fp16 MMA (1 term), fp32 accum.
// 3-stage cp.async pipeline, single top barrier, 2 CTAs/SM.
// K-chunk 64 halves barrier count vs K=32 (4 k-subtiles per barrier).

static constexpr int A_STRIDE = 72;                 // 16-bit units (144 B, 9*16)
static constexpr int A_PLANE  = 128 * A_STRIDE;     // 9216
static constexpr int B_BASE   = 3 * A_PLANE;        // 27648
static constexpr int B_STRIDE = 136;                // 16-bit units (272 B, 17*16)
static constexpr int B_PLANE  = 64 * B_STRIDE;      // 8704
static constexpr int SMEM_U16 = B_BASE + 3 * B_PLANE;        // 53760
static constexpr int GEMM_SMEM_BYTES = SMEM_U16 * 2;         // 107520

__device__ __forceinline__ uint32_t smem_u32(const void* p) {
    uint32_t a;
    asm("{ .reg .u64 t; cvta.to.shared.u64 t, %1; cvt.u32.u64 %0, t; }"
        : "=r"(a) : "l"(p));
    return a;
}

__device__ __forceinline__ void cp16(uint32_t dst, const void* src) {
    asm volatile("cp.async.cg.shared.global [%0], [%1], 16;"
                 :: "r"(dst), "l"(src) : "memory");
}
#define CP_COMMIT() asm volatile("cp.async.commit_group;" ::: "memory")
#define CP_WAIT1()  asm volatile("cp.async.wait_group 1;" ::: "memory")

__device__ __forceinline__ void ldsm4(uint32_t* r, uint32_t addr) {
    asm volatile("ldmatrix.sync.aligned.m8n8.x4.shared.b16 {%0,%1,%2,%3}, [%4];"
                 : "=r"(r[0]), "=r"(r[1]), "=r"(r[2]), "=r"(r[3]) : "r"(addr));
}
__device__ __forceinline__ void ldsm4t(uint32_t* r, uint32_t addr) {
    asm volatile("ldmatrix.sync.aligned.m8n8.x4.trans.shared.b16 {%0,%1,%2,%3}, [%4];"
                 : "=r"(r[0]), "=r"(r[1]), "=r"(r[2]), "=r"(r[3]) : "r"(addr));
}

__device__ __forceinline__ void mma_f16(float* d, const uint32_t* a,
                                        const uint32_t* b) {
    asm volatile(
        "mma.sync.aligned.m16n8k16.row.col.f32.f16.f16.f32 "
        "{%0,%1,%2,%3}, {%4,%5,%6,%7}, {%8,%9}, {%0,%1,%2,%3};"
        : "+f"(d[0]), "+f"(d[1]), "+f"(d[2]), "+f"(d[3])
        : "r"(a[0]), "r"(a[1]), "r"(a[2]), "r"(a[3]), "r"(b[0]), "r"(b[1]));
}

__device__ __forceinline__ void red_v2(float* ptr, float v0, float v1) {
    asm volatile("red.global.add.v2.f32 [%0], {%1, %2};"
                 :: "l"(ptr), "f"(v0), "f"(v1) : "memory");
}

// NCH chunks of K=64 per CTA per K-slice. GATHER: A rows via g_idx (lda=ND).
// GELU_EPI: write fp16 gelu(acc+bias); else scatter-add into fp32 outa.
// blockIdx.z = K-slice; slice 0 adds bias. Ktot = full K (B expert stride).
template<int NCH, bool GATHER, bool GELU_EPI>
__global__ __launch_bounds__(256, 2) void gemm_tc_kernel(
    const uint16_t* __restrict__ Ah,
    const uint16_t* __restrict__ Bh,
    const float* __restrict__ bias,
    float* __restrict__ outa,
    __half* __restrict__ outbh,
    int Nld, int lda, int Ktot) {
    extern __shared__ __align__(16) uint16_t sm[];
    __shared__ int   tok_s[128];
    __shared__ float val_s[128];

    const int tid = threadIdx.x;
    const int warp = tid >> 5;
    const int lane = tid & 31;
    const int wm = warp >> 2;          // 0..1  (64-row slab)
    const int wn = warp & 3;           // 0..3  (32-col slab)
    const int r = lane >> 2;           // 0..7 (accumulator row)
    const int c = lane & 3;            // 0..3 (accumulator col pair)
    const int quad = lane >> 3;        // 0..3 (ldmatrix matrix id)
    const int r8 = lane & 7;           // row within 8x8 matrix

    const int n0 = blockIdx.x * 128;
    const int m0 = blockIdx.y * 128;
    const int e = m0 >> 11;            // m0 / NC
    const int kbase = blockIdx.z * NCH * 64;
    const bool bias_en = (blockIdx.z == 0);

    if (tid < 128) {
        tok_s[tid] = g_idx[m0 + tid];
        val_s[tid] = g_vals[m0 + tid];
    }
    __syncthreads();

    const uint32_t sbase = smem_u32(sm);

    // ---- precomputed load pointers (advance one K-chunk per load_stage) ----
    const uint16_t* asrc[4];           // A: 128 rows x 8 segs = 1024 cp16
    uint32_t adst0[4];
    const uint16_t* bsrc[4];           // B: 64 rows x 16 segs = 1024 cp16
    uint32_t bdst0[4];
    {
        const uint16_t* bp = Bh + (size_t)e * Ktot * Nld + n0;
#pragma unroll
        for (int i = 0; i < 4; i++) {              // A: 128 rows x 8 segs
            int lin = tid + 256 * i;
            int row = lin >> 3;
            int seg = (lin & 7) * 8;
            asrc[i] = GATHER
                ? (Ah + (size_t)tok_s[row] * lda + kbase + seg)
                : (Ah + (size_t)(m0 + row) * lda + kbase + seg);
            adst0[i] = sbase + (uint32_t)(row * A_STRIDE + seg) * 2;
        }
#pragma unroll
        for (int i = 0; i < 4; i++) {              // B: 64 rows x 16 segs
            int lin = tid + 256 * i;
            int row = lin >> 4;                    // 0..63
            int seg = (lin & 15) * 8;
            bsrc[i] = bp + (size_t)(kbase + row) * Nld + seg;
            bdst0[i] = sbase + (uint32_t)(B_BASE + row * B_STRIDE + seg) * 2;
        }
    }

    auto load_stage = [&](int s) {
        const uint32_t ao = (uint32_t)s * (A_PLANE * 2);
        const uint32_t bo = (uint32_t)s * (B_PLANE * 2);
#pragma unroll
        for (int j = 0; j < 4; j++) {
            cp16(adst0[j] + ao, asrc[j]);
            asrc[j] += 64;
        }
#pragma unroll
        for (int j = 0; j < 4; j++) {
            cp16(bdst0[j] + bo, bsrc[j]);
            bsrc[j] += (size_t)64 * Nld;
        }
    };

    float acc[4][4][4];                // [mt][nt][frag]
#pragma unroll
    for (int mt = 0; mt < 4; mt++)
#pragma unroll
        for (int nt = 0; nt < 4; nt++)
#pragma unroll
            for (int i = 0; i < 4; i++) acc[mt][nt][i] = 0.0f;

    // prologue: fill stages 0, 1 (prefetch distance 2)
    load_stage(0);
    CP_COMMIT();
    load_stage(1);
    CP_COMMIT();

    int s = 0;                         // current stage, wraps mod 3
    int sload = 2;                     // stage to load next, wraps mod 3
#pragma unroll 1
    for (int ch = 0; ch < NCH; ch++) {
        CP_WAIT1();
        __syncthreads();               // single barrier: also guards stage reuse
        if (ch + 2 < NCH) load_stage(sload);
        CP_COMMIT();   // unconditional: keeps wait_group bookkeeping exact

        const uint32_t sa = sbase + (uint32_t)s * (A_PLANE * 2);
        const uint32_t sb = sbase + (uint32_t)(B_BASE * 2 + s * (B_PLANE * 2));
#pragma unroll
        for (int ks = 0; ks < 4; ks++) {
            // ---- A fragments: 4 m-tiles via ldmatrix.x4 ----
            uint32_t ah[4][4];
            {
                const int m_local = wm * 64 + (quad & 1) * 8 + r8;
                const int k_off = ks * 16 + (quad >> 1) * 8;
                const uint32_t abase = sa +
                    (uint32_t)(m_local * A_STRIDE + k_off) * 2;
#pragma unroll
                for (int mt = 0; mt < 4; mt++)
                    ldsm4(ah[mt], abase + (uint32_t)(mt * 16 * A_STRIDE) * 2);
            }
            // ---- B fragments per 16-col group ----
            {
                const int k_row = ks * 16 + (quad & 1) * 8 + r8;
                const int n_col = wn * 32 + (quad >> 1) * 8;
                const uint32_t bbase = sb +
                    (uint32_t)(k_row * B_STRIDE + n_col) * 2;
#pragma unroll
                for (int nt2 = 0; nt2 < 2; nt2++) {
                    uint32_t bh[4];
                    ldsm4t(bh, bbase + (uint32_t)(nt2 * 16) * 2);
                    const int nt = nt2 * 2;
#pragma unroll
                    for (int mt = 0; mt < 4; mt++) {
                        mma_f16(acc[mt][nt],     ah[mt], bh);
                        mma_f16(acc[mt][nt + 1], ah[mt], bh + 2);
                    }
                }
            }
        }
        s = (s == 2) ? 0 : s + 1;
        sload = (sload == 2) ? 0 : sload + 1;
    }

    // ---------------- epilogue -----------------------------------------------
#pragma unroll
    for (int mt = 0; mt < 4; mt++) {
        const int lm0 = wm * 64 + mt * 16 + r;       // local row of acc[0],acc[1]
        const int lm1 = lm0 + 8;                     // local row of acc[2],acc[3]
#pragma unroll
        for (int nt = 0; nt < 4; nt++) {
            const int bcol = n0 + wn * 32 + nt * 8 + c * 2;
            const float bb0 = bias_en ? bias[e * Nld + bcol] : 0.0f;
            const float bb1 = bias_en ? bias[e * Nld + bcol + 1] : 0.0f;
            if (GELU_EPI) {
                __half2 hp0 = __floats2half2_rn(gelu_f(acc[mt][nt][0] + bb0),
                                                gelu_f(acc[mt][nt][1] + bb1));
                __half2 hp1 = __floats2half2_rn(gelu_f(acc[mt][nt][2] + bb0),
                                                gelu_f(acc[mt][nt][3] + bb1));
                *(__half2*)(outbh + (size_t)(m0 + lm0) * Nld + bcol) = hp0;
                *(__half2*)(outbh + (size_t)(m0 + lm1) * Nld + bcol) = hp1;
            } else {
                const float w0 = val_s[lm0];
                const float w1 = val_s[lm1];
                float* p0 = outa + (size_t)tok_s[lm0] * ND + bcol;
                float* p1 = outa + (size_t)tok_s[lm1] * ND + bcol;
                red_v2(p0, (acc[mt][nt][0] + bb0) * w0, (acc[mt][nt][1] + bb1) * w0);
                red_v2(p1, (acc[mt][nt][2] + bb0) * w1, (acc[mt][nt][3] + bb1) * w1);
            }
        }
    }
}

// ============================ host launch =====================================
extern "C" void kernel_launch(void* const* d_in, const int* in_sizes, int n_in,
                              void* d_out, int out_size) {
    const float* x  = (const float*)d_in[0];   // [T, D]
    const float* Wg = (const float*)d_in[1];   // [D, E]
    const float* W1 = (const float*)d_in[2];   // [E, D, F]
    const float* b1 = (const float*)d_in[3];   // [E, F]
    const float* W2 = (const float*)d_in[4];   // [E, F, D]
    const float* b2 = (const float*)d_in[5];   // [E, D]
    float* out = (float*)d_out;

    void *p_xh, *p_w1h, *p_w2h, *p_hh;
    cudaGetSymbolAddress(&p_xh, g_xh);
    cudaGetSymbolAddress(&p_w1h, g_w1h);
    cudaGetSymbolAddress(&p_w2h, g_w2h);
    cudaGetSymbolAddress(&p_hh, g_hh);

    cudaFuncSetAttribute(
        (const void*)gemm_tc_kernel<16, true, true>,
        cudaFuncAttributeMaxDynamicSharedMemorySize, GEMM_SMEM_BYTES);
    cudaFuncSetAttribute(
        (const void*)gemm_tc_kernel<32, false, false>,
        cudaFuncAttributeMaxDynamicSharedMemorySize, GEMM_SMEM_BYTES);

    size_t n_main = (size_t)NT * ND;
    init_out_kernel<<<512, 256>>>(out, n_main, (size_t)out_size);
    router_kernel<<<NT / 32, 1024>>>(x, Wg);
    topk_kernel<<<NE, 1024>>>();

    // Convert operands to fp16.
    cvt_f16_kernel<<<(NT * ND / 8 + 255) / 256, 256>>>(
        (const float4*)x, (uint4*)p_xh, (size_t)NT * ND / 8);
    cvt_f16_kernel<<<((size_t)NE * ND * NF / 8 + 255) / 256, 256>>>(
        (const float4*)W1, (uint4*)p_w1h, (size_t)NE * ND * NF / 8);
    cvt_f16_kernel<<<((size_t)NE * NF * ND / 8 + 255) / 256, 256>>>(
        (const float4*)W2, (uint4*)p_w2h, (size_t)NE * NF * ND / 8);

    // GEMM1: h = gelu(x[idx] @ W1[e] + b1[e])   fp16, K-chunk 64, 16 chunks
    gemm_tc_kernel<16, true, true>
        <<<dim3(NF / 128, NM / 128, 1), 256, GEMM_SMEM_BYTES>>>(
            (const uint16_t*)p_xh, (const uint16_t*)p_w1h,
            b1, nullptr, (__half*)p_hh, NF, ND, ND);

    // GEMM2: out[tok] += val*(h @ W2[e] + b2[e])   fp16, split-K=2, 32 chunks
    gemm_tc_kernel<32, false, false>
        <<<dim3(ND / 128, NM / 128, 2), 256, GEMM_SMEM_BYTES>>>(
            (const uint16_t*)p_hh, (const uint16_t*)p_w2h,
            b2, out, nullptr, ND, NF, NF);
}